// round 8
// baseline (speedup 1.0000x reference)
#include <cuda_runtime.h>
#include <cuda_bf16.h>
#include <math.h>
#include <stdint.h>

#define NNODES 32768
#define NEDGES 524288
#define NB     32
#define NPG    1024
#define CH     128
#define CIN    64
#define SLOTCAP 64
#define PITCH  136   // halves per row in stack2 smem tiles (128 + 8 pad)

// ================= helpers =================
__device__ __forceinline__ uint32_t smem_u32(const void* p) {
    uint32_t a;
    asm("{ .reg .u64 t; cvta.to.shared.u64 t, %1; cvt.u32.u64 %0, t; }" : "=r"(a) : "l"(p));
    return a;
}
#define CP_ASYNC16(dst, src) asm volatile("cp.async.ca.shared.global [%0], [%1], 16;" :: "r"(dst), "l"(src))
#define CP_COMMIT()          asm volatile("cp.async.commit_group;" ::: "memory")
#define CP_WAIT(n)           asm volatile("cp.async.wait_group %0;" :: "n"(n) : "memory")

#define MMA_BF16(cf, a0, a1, a2, a3, b0, b1) \
    asm volatile("mma.sync.aligned.m16n8k16.row.col.f32.bf16.bf16.f32 " \
        "{%0,%1,%2,%3},{%4,%5,%6,%7},{%8,%9},{%0,%1,%2,%3};" \
        : "+f"((cf)[0]), "+f"((cf)[1]), "+f"((cf)[2]), "+f"((cf)[3]) \
        : "r"(a0), "r"(a1), "r"(a2), "r"(a3), "r"(b0), "r"(b1))

__device__ __forceinline__ uint32_t pack_hi(float a, float b) {
    __nv_bfloat162 h;
    h.x = __float2bfloat16_rn(a); h.y = __float2bfloat16_rn(b);
    return *reinterpret_cast<uint32_t*>(&h);
}
__device__ __forceinline__ uint32_t pack_lo(float a, float b) {
    __nv_bfloat16 ha = __float2bfloat16_rn(a), hb = __float2bfloat16_rn(b);
    __nv_bfloat162 l;
    l.x = __float2bfloat16_rn(a - __bfloat162float(ha));
    l.y = __float2bfloat16_rn(b - __bfloat162float(hb));
    return *reinterpret_cast<uint32_t*>(&l);
}
__device__ __forceinline__ void split1(float v, __nv_bfloat16& h, __nv_bfloat16& l) {
    h = __float2bfloat16_rn(v);
    l = __float2bfloat16_rn(v - __bfloat162float(h));
}

// ================= device scratch =================
__device__ int   g_deg[NNODES];
__device__ int   g_srcbuf[NNODES * SLOTCAP];
__device__ float g_dinv[NNODES];

__device__ float g_lin[NNODES * CH];
__device__ float g_y  [NNODES * CH];
__device__ float g_h  [NNODES * CH];
__device__ float g_s  [NNODES * CH];

__device__ __align__(16) __nv_bfloat16 g_axh[NNODES * CIN], g_axl[NNODES * CIN];
__device__ __align__(16) __nv_bfloat16 g_hah[NNODES * CH],  g_hal[NNODES * CH];
__device__ __align__(16) __nv_bfloat16 g_hbh[NNODES * CH],  g_hbl[NNODES * CH];
__device__ __align__(16) __nv_bfloat16 g_hTh[CH * NNODES],  g_hTl[CH * NNODES];
__device__ __align__(16) __nv_bfloat16 g_sTh[CH * NNODES],  g_sTl[CH * NNODES];
__device__ __align__(16) __nv_bfloat16 g_tTh[CH * NNODES],  g_tTl[CH * NNODES];
__device__ __align__(16) __nv_bfloat16 g_w1ah[CH * CIN], g_w1al[CH * CIN];
__device__ __align__(16) __nv_bfloat16 g_w1bh[CH * CH],  g_w1bl[CH * CH];
__device__ __align__(16) __nv_bfloat16 g_wp1h[CH * CH],  g_wp1l[CH * CH];

__device__ float g_xpart[8 * NB * CH * CH];
__device__ float g_apart[8 * NB * CH * CH];
__device__ float g_x2  [NB * CH * CH];
__device__ float g_A2  [NB * CH * CH];
__device__ float g_An  [NB * CH * CH];

__device__ float g_sumA[CH], g_ssA[CH], g_sumB[CH], g_ssB[CH];
__device__ float g_s2a[CH], g_q2a[CH], g_s2b[CH], g_q2b[CH];
__device__ int   g_bar;

// ================= graph structure (one-pass bucket CSR) =================
__global__ void k_zero_deg() {
    int i = blockIdx.x * 256 + threadIdx.x;
    g_deg[i] = 0;
    if (i < 128) { g_sumA[i] = 0.f; g_ssA[i] = 0.f; g_sumB[i] = 0.f; g_ssB[i] = 0.f; }
}
__global__ void k_build(const int* __restrict__ ei) {
    int e = blockIdx.x * 256 + threadIdx.x;
    if (e < NEDGES) {
        int d = ei[NEDGES + e];
        int p = atomicAdd(&g_deg[d], 1);
        g_srcbuf[d * SLOTCAP + p] = ei[e];
    }
}

// weights transpose + bf16 split; also dinv (needs deg -> after k_build)
__global__ void k_wsplit(const float* __restrict__ w1a, const float* __restrict__ w1b,
                         const float* __restrict__ wp1) {
    int idx = blockIdx.x * 256 + threadIdx.x;      // 160 blocks = 40960
    if (idx < NNODES) g_dinv[idx] = rsqrtf((float)g_deg[idx] + 1.0f);
    if (idx < 8192) {
        int n = idx >> 6, k = idx & 63;
        split1(w1a[k * 128 + n], g_w1ah[idx], g_w1al[idx]);
    } else if (idx < 24576) {
        int j = idx - 8192;
        int n = j >> 7, k = j & 127;
        split1(w1b[k * 128 + n], g_w1bh[j], g_w1bl[j]);
    } else if (idx < 40960) {
        int j = idx - 24576;
        int n = j >> 7, k = j & 127;
        split1(wp1[k * 128 + n], g_wp1h[j], g_wp1l[j]);
    }
}

// ================= bf16-split mma.sync GEMM (stack 1 + pooled) =================
template<bool POOLED, bool STATS>
__global__ __launch_bounds__(256) void k_mma(
    const __nv_bfloat16* __restrict__ Ah, const __nv_bfloat16* __restrict__ Al, long long pA,
    const __nv_bfloat16* __restrict__ B1h, const __nv_bfloat16* __restrict__ B1l,
    const __nv_bfloat16* __restrict__ B2h, const __nv_bfloat16* __restrict__ B2l, long long pB,
    const float* __restrict__ bias, float* __restrict__ C1, float* __restrict__ C2, int K)
{
    extern __shared__ __align__(16) char smem[];
    __nv_bfloat16* SB = reinterpret_cast<__nv_bfloat16*>(smem);
    float* sstat = reinterpret_cast<float*>(smem + 49152);
    int t = threadIdx.x, lane = t & 31;
    int warpm = ((t >> 5) & 3) * 32, warpn = (t >> 7) * 64;

    const __nv_bfloat16 *Ahb, *Alb, *Bhb, *Blb;
    float* Cb;
    if (POOLED) {
        int g = blockIdx.z;
        int half = blockIdx.y >> 3, chunk = blockIdx.y & 7;
        long long ko = (long long)g * 1024 + (long long)chunk * 128;
        Ahb = Ah + ko; Alb = Al + ko;
        Bhb = (half ? B2h : B1h) + ko;
        Blb = (half ? B2l : B1l) + ko;
        Cb = (half ? C2 : C1) + (long long)(chunk * NB + g) * (CH * CH);
    } else {
        long long m0 = (long long)blockIdx.x * 128;
        Ahb = Ah + m0 * pA; Alb = Al + m0 * pA;
        Bhb = B1h; Blb = B1l;
        Cb = C1 + m0 * 128;
    }
    if (STATS) { sstat[t] = 0.f; }

    uint32_t sbase = smem_u32(SB);
    int sr = t >> 1, sc = t & 1;
    uint32_t dofs = sbase + sr * 48 + sc * 16;
    CP_ASYNC16(dofs,         Ahb + (long long)sr * pA + sc * 8);
    CP_ASYNC16(dofs + 6144,  Alb + (long long)sr * pA + sc * 8);
    CP_ASYNC16(dofs + 12288, Bhb + (long long)sr * pB + sc * 8);
    CP_ASYNC16(dofs + 18432, Blb + (long long)sr * pB + sc * 8);
    CP_COMMIT();

    float c[2][8][4];
#pragma unroll
    for (int i = 0; i < 2; i++)
#pragma unroll
        for (int j = 0; j < 8; j++)
#pragma unroll
            for (int q = 0; q < 4; q++) c[i][j][q] = 0.f;

    int g8 = lane >> 2, kc = (lane & 3) * 2;
    int NT = K >> 4;
    for (int kt = 0; kt < NT; kt++) {
        if (kt + 1 < NT) {
            int k0 = (kt + 1) << 4;
            uint32_t d2 = dofs + ((kt + 1) & 1) * 24576;
            CP_ASYNC16(d2,         Ahb + (long long)sr * pA + k0 + sc * 8);
            CP_ASYNC16(d2 + 6144,  Alb + (long long)sr * pA + k0 + sc * 8);
            CP_ASYNC16(d2 + 12288, Bhb + (long long)sr * pB + k0 + sc * 8);
            CP_ASYNC16(d2 + 18432, Blb + (long long)sr * pB + k0 + sc * 8);
            CP_COMMIT();
            CP_WAIT(1);
        } else {
            CP_WAIT(0);
        }
        __syncthreads();
        const __nv_bfloat16* P = SB + (kt & 1) * 12288;
        uint32_t ah[2][4], al[2][4];
#pragma unroll
        for (int mt = 0; mt < 2; mt++) {
            int mb = warpm + mt * 16 + g8;
            ah[mt][0] = *(const uint32_t*)(P + mb * 24 + kc);
            ah[mt][1] = *(const uint32_t*)(P + (mb + 8) * 24 + kc);
            ah[mt][2] = *(const uint32_t*)(P + mb * 24 + kc + 8);
            ah[mt][3] = *(const uint32_t*)(P + (mb + 8) * 24 + kc + 8);
            al[mt][0] = *(const uint32_t*)(P + 3072 + mb * 24 + kc);
            al[mt][1] = *(const uint32_t*)(P + 3072 + (mb + 8) * 24 + kc);
            al[mt][2] = *(const uint32_t*)(P + 3072 + mb * 24 + kc + 8);
            al[mt][3] = *(const uint32_t*)(P + 3072 + (mb + 8) * 24 + kc + 8);
        }
#pragma unroll
        for (int nt = 0; nt < 8; nt++) {
            int nb = warpn + nt * 8 + g8;
            uint32_t bh0 = *(const uint32_t*)(P + 6144 + nb * 24 + kc);
            uint32_t bh1 = *(const uint32_t*)(P + 6144 + nb * 24 + kc + 8);
            uint32_t bl0 = *(const uint32_t*)(P + 9216 + nb * 24 + kc);
            uint32_t bl1 = *(const uint32_t*)(P + 9216 + nb * 24 + kc + 8);
#pragma unroll
            for (int mt = 0; mt < 2; mt++) {
                MMA_BF16(c[mt][nt], ah[mt][0], ah[mt][1], ah[mt][2], ah[mt][3], bh0, bh1);
                MMA_BF16(c[mt][nt], ah[mt][0], ah[mt][1], ah[mt][2], ah[mt][3], bl0, bl1);
                MMA_BF16(c[mt][nt], al[mt][0], al[mt][1], al[mt][2], al[mt][3], bh0, bh1);
            }
        }
        __syncthreads();
    }

    float cs[8][2], cq[8][2];
    if (STATS) {
#pragma unroll
        for (int j = 0; j < 8; j++) { cs[j][0] = cs[j][1] = 0.f; cq[j][0] = cq[j][1] = 0.f; }
    }
#pragma unroll
    for (int mt = 0; mt < 2; mt++) {
        int row = warpm + mt * 16 + g8;
#pragma unroll
        for (int nt = 0; nt < 8; nt++) {
            int col = warpn + nt * 8 + kc;
            float b0 = bias ? bias[col] : 0.f;
            float b1 = bias ? bias[col + 1] : 0.f;
            float v00 = c[mt][nt][0] + b0, v01 = c[mt][nt][1] + b1;
            float v10 = c[mt][nt][2] + b0, v11 = c[mt][nt][3] + b1;
            *reinterpret_cast<float2*>(Cb + (long long)row * 128 + col) = make_float2(v00, v01);
            *reinterpret_cast<float2*>(Cb + (long long)(row + 8) * 128 + col) = make_float2(v10, v11);
            if (STATS) {
                cs[nt][0] += v00 + v10; cq[nt][0] += v00 * v00 + v10 * v10;
                cs[nt][1] += v01 + v11; cq[nt][1] += v01 * v01 + v11 * v11;
            }
        }
    }
    if (STATS) {
        __syncthreads();
#pragma unroll
        for (int nt = 0; nt < 8; nt++) {
            int col = warpn + nt * 8 + kc;
            atomicAdd(&sstat[col], cs[nt][0]);
            atomicAdd(&sstat[col + 1], cs[nt][1]);
            atomicAdd(&sstat[128 + col], cq[nt][0]);
            atomicAdd(&sstat[128 + col + 1], cq[nt][1]);
        }
        __syncthreads();
        if (t < 128) {
            atomicAdd(&g_sumA[t], sstat[t]);
            atomicAdd(&g_ssA[t], sstat[128 + t]);
        }
    }
}

// ================= warp-per-node aggregation =================
template<int MODE>
__global__ __launch_bounds__(256) void k_aggw(
    const float* __restrict__ in, const float* __restrict__ bias, float* __restrict__ out,
    __nv_bfloat16* __restrict__ oTh, __nv_bfloat16* __restrict__ oTl)
{
    __shared__ float sred[8][128];
    __shared__ float st[8][132];
    int t = threadIdx.x, w = t >> 5, lane = t & 31;
    int i = blockIdx.x * 8 + w;
    int e0 = i * SLOTCAP, n = g_deg[i];
    float ax = 0.f, ay = 0.f, az = 0.f, aw = 0.f;
    for (int c0 = 0; c0 < n; c0 += 32) {
        int m = n - c0; if (m > 32) m = 32;
        int src = 0; float dv = 0.f;
        if (lane < m) {
            src = g_srcbuf[e0 + c0 + lane];
            if (MODE != 2) dv = g_dinv[src];
        }
        for (int kk = 0; kk < m; kk++) {
            int s = __shfl_sync(0xffffffffu, src, kk);
            float4 hv = *reinterpret_cast<const float4*>(in + (long long)s * 128 + lane * 4);
            if (MODE == 2) {
                ax += hv.x; ay += hv.y; az += hv.z; aw += hv.w;
            } else {
                float d = __shfl_sync(0xffffffffu, dv, kk);
                ax += d * hv.x; ay += d * hv.y; az += d * hv.z; aw += d * hv.w;
            }
        }
    }
    float vx, vy, vz, vw;
    if (MODE != 2) {
        float di = g_dinv[i];
        float4 hv = *reinterpret_cast<const float4*>(in + (long long)i * 128 + lane * 4);
        vx = di * (ax + di * hv.x) + bias[lane * 4 + 0];
        vy = di * (ay + di * hv.y) + bias[lane * 4 + 1];
        vz = di * (az + di * hv.z) + bias[lane * 4 + 2];
        vw = di * (aw + di * hv.w) + bias[lane * 4 + 3];
    } else {
        vx = ax; vy = ay; vz = az; vw = aw;
    }
    if (MODE == 1) {
        float mx = fmaxf(fmaxf(vx, vy), fmaxf(vz, vw));
#pragma unroll
        for (int o = 16; o; o >>= 1) mx = fmaxf(mx, __shfl_xor_sync(0xffffffffu, mx, o));
        vx = __expf(vx - mx); vy = __expf(vy - mx); vz = __expf(vz - mx); vw = __expf(vw - mx);
        float sm = vx + vy + vz + vw;
#pragma unroll
        for (int o = 16; o; o >>= 1) sm += __shfl_xor_sync(0xffffffffu, sm, o);
        float inv = 1.f / sm;
        vx *= inv; vy *= inv; vz *= inv; vw *= inv;
    }
    if (MODE != 2) {
        float4 o4 = { vx, vy, vz, vw };
        *reinterpret_cast<float4*>(out + (long long)i * 128 + lane * 4) = o4;
    }
    if (MODE == 0) {
        sred[w][lane * 4 + 0] = vx; sred[w][lane * 4 + 1] = vy;
        sred[w][lane * 4 + 2] = vz; sred[w][lane * 4 + 3] = vw;
        __syncthreads();
        if (t < 128) {
            float s = 0.f, q = 0.f;
#pragma unroll
            for (int ww = 0; ww < 8; ww++) { float v = sred[ww][t]; s += v; q += v * v; }
            atomicAdd(&g_sumB[t], s);
            atomicAdd(&g_ssB[t], q);
        }
    } else {
        st[w][lane * 4 + 0] = vx; st[w][lane * 4 + 1] = vy;
        st[w][lane * 4 + 2] = vz; st[w][lane * 4 + 3] = vw;
        __syncthreads();
        if (t < 128) {
            int c = t;
            float v0 = st[0][c], v1 = st[1][c], v2 = st[2][c], v3 = st[3][c];
            float v4 = st[4][c], v5 = st[5][c], v6 = st[6][c], v7 = st[7][c];
            long long o = (long long)c * NNODES + blockIdx.x * 8;
            uint4 hv, lv;
            hv.x = pack_hi(v0, v1); hv.y = pack_hi(v2, v3);
            hv.z = pack_hi(v4, v5); hv.w = pack_hi(v6, v7);
            lv.x = pack_lo(v0, v1); lv.y = pack_lo(v2, v3);
            lv.z = pack_lo(v4, v5); lv.w = pack_lo(v6, v7);
            *reinterpret_cast<uint4*>(oTh + o) = hv;
            *reinterpret_cast<uint4*>(oTl + o) = lv;
        }
    }
}

// agg of x (64 ch) -> row-major bf16 hi/lo
__global__ __launch_bounds__(256) void k_aggx(const float* __restrict__ x) {
    int t = threadIdx.x, w = t >> 5, lane = t & 31;
    int i = blockIdx.x * 8 + w;
    int e0 = i * SLOTCAP, n = g_deg[i];
    float ax = 0.f, ay = 0.f;
    for (int c0 = 0; c0 < n; c0 += 32) {
        int m = n - c0; if (m > 32) m = 32;
        int src = 0; float dv = 0.f;
        if (lane < m) { src = g_srcbuf[e0 + c0 + lane]; dv = g_dinv[src]; }
        for (int kk = 0; kk < m; kk++) {
            int s = __shfl_sync(0xffffffffu, src, kk);
            float d = __shfl_sync(0xffffffffu, dv, kk);
            float2 hv = *reinterpret_cast<const float2*>(x + (long long)s * 64 + lane * 2);
            ax += d * hv.x; ay += d * hv.y;
        }
    }
    float di = g_dinv[i];
    float2 hv = *reinterpret_cast<const float2*>(x + (long long)i * 64 + lane * 2);
    ax = di * (ax + di * hv.x);
    ay = di * (ay + di * hv.y);
    long long o = (long long)i * 64 + lane * 2;
    *reinterpret_cast<uint32_t*>(g_axh + o) = pack_hi(ax, ay);
    *reinterpret_cast<uint32_t*>(g_axl + o) = pack_lo(ax, ay);
}

// ================= BN+SiLU(+res); fp32 h (opt), row bf16, trans bf16 (opt) =================
template<bool RES, bool WH, bool WT>
__global__ __launch_bounds__(256) void k_bn(
    const float* __restrict__ y, const float* __restrict__ res, float* __restrict__ h,
    __nv_bfloat16* __restrict__ rh, __nv_bfloat16* __restrict__ rl,
    __nv_bfloat16* __restrict__ th, __nv_bfloat16* __restrict__ tl,
    const float* __restrict__ gw, const float* __restrict__ be,
    const float* __restrict__ sumArr, const float* __restrict__ ssArr)
{
    __shared__ float tile[32][33];
    __shared__ float sc[32], sh[32];
    int t = threadIdx.x;
    int n0 = blockIdx.x * 32, c0 = blockIdx.y * 32;
    if (t < 32) {
        int c = c0 + t;
        float m = sumArr[c] * (1.f / NNODES);
        float var = ssArr[c] * (1.f / NNODES) - m * m;
        float s = gw[c] * rsqrtf(var + 1e-5f);
        sc[t] = s;
        sh[t] = be[c] - s * m;
    }
    __syncthreads();
    int nl = t >> 3, cg = t & 7;
    long long idx = (long long)(n0 + nl) * 128 + c0 + cg * 4;
    float4 v = *reinterpret_cast<const float4*>(y + idx);
    float o0, o1, o2, o3;
    {
        float a;
        a = sc[cg * 4 + 0] * v.x + sh[cg * 4 + 0]; o0 = a / (1.f + __expf(-a));
        a = sc[cg * 4 + 1] * v.y + sh[cg * 4 + 1]; o1 = a / (1.f + __expf(-a));
        a = sc[cg * 4 + 2] * v.z + sh[cg * 4 + 2]; o2 = a / (1.f + __expf(-a));
        a = sc[cg * 4 + 3] * v.w + sh[cg * 4 + 3]; o3 = a / (1.f + __expf(-a));
    }
    if (RES) {
        float4 r = *reinterpret_cast<const float4*>(res + idx);
        o0 += r.x; o1 += r.y; o2 += r.z; o3 += r.w;
    }
    if (WH) {
        float4 ov = { o0, o1, o2, o3 };
        *reinterpret_cast<float4*>(h + idx) = ov;
    }
    {
        uint2 hv, lv;
        hv.x = pack_hi(o0, o1); hv.y = pack_hi(o2, o3);
        lv.x = pack_lo(o0, o1); lv.y = pack_lo(o2, o3);
        *reinterpret_cast<uint2*>(rh + idx) = hv;
        *reinterpret_cast<uint2*>(rl + idx) = lv;
    }
    if (WT) {
        tile[nl][cg * 4 + 0] = o0; tile[nl][cg * 4 + 1] = o1;
        tile[nl][cg * 4 + 2] = o2; tile[nl][cg * 4 + 3] = o3;
        __syncthreads();
        int cc = t >> 3, g = t & 7;
        float w0 = tile[g * 4 + 0][cc], w1 = tile[g * 4 + 1][cc];
        float w2 = tile[g * 4 + 2][cc], w3 = tile[g * 4 + 3][cc];
        long long o = (long long)(c0 + cc) * NNODES + n0 + g * 4;
        uint2 hv, lv;
        hv.x = pack_hi(w0, w1); hv.y = pack_hi(w2, w3);
        lv.x = pack_lo(w0, w1); lv.y = pack_lo(w2, w3);
        *reinterpret_cast<uint2*>(th + o) = hv;
        *reinterpret_cast<uint2*>(tl + o) = lv;
    }
}

// ================= reduce partials + dinv2 + An; reset stack-2 state =================
__global__ __launch_bounds__(256) void k_reduce_an() {
    int b = blockIdx.x, t = threadIdx.x;
    if (b == 0 && t < 128) {
        g_s2a[t] = 0.f; g_q2a[t] = 0.f; g_s2b[t] = 0.f; g_q2b[t] = 0.f;
        if (t == 0) g_bar = 0;
    }
    const long long PS = (long long)NB * CH * CH;
    const long long BO = (long long)b * CH * CH;
    __shared__ float sd[128];
    for (int idx = t; idx < CH * CH; idx += 256) {
        float s = 0.f;
#pragma unroll
        for (int p = 0; p < 8; p++) s += g_xpart[p * PS + BO + idx];
        g_x2[BO + idx] = s;
    }
    int w = t >> 5, lane = t & 31;
    for (int r = w; r < 128; r += 8) {
        float rsum = 0.f;
#pragma unroll
        for (int q = 0; q < 4; q++) {
            int idx = r * 128 + lane + q * 32;
            float s = 0.f;
#pragma unroll
            for (int p = 0; p < 8; p++) s += g_apart[p * PS + BO + idx];
            g_A2[BO + idx] = s;
            rsum += s;
        }
#pragma unroll
        for (int o = 16; o; o >>= 1) rsum += __shfl_down_sync(0xffffffffu, rsum, o);
        if (lane == 0) sd[r] = rsqrtf(rsum + 1.0f);
    }
    __syncthreads();
    for (int idx = t; idx < CH * CH; idx += 256) {
        int i = idx >> 7, j = idx & 127;
        float v = g_A2[BO + idx] + (i == j ? 1.f : 0.f);
        g_An[BO + idx] = sd[i] * v * sd[j];
    }
}

// ================= fused stack-2: mma.sync in smem, grid barrier =================
__device__ __forceinline__ void gridbar(int target) {
    __syncthreads();
    __threadfence();
    if (threadIdx.x == 0) {
        atomicAdd(&g_bar, 1);
        while (*(volatile int*)&g_bar < target) __nanosleep(64);
    }
    __syncthreads();
    __threadfence();
}

// C = A @ B^T over K=128: A,B bf16 hi/lo in smem with PITCH rows.
__device__ __forceinline__ void mma_sm(
    const __nv_bfloat16* Ah, const __nv_bfloat16* Al,
    const __nv_bfloat16* Bh, const __nv_bfloat16* Bl,
    float c[2][8][4], int warpm, int warpn, int g8, int kc)
{
#pragma unroll
    for (int i = 0; i < 2; i++)
#pragma unroll
        for (int j = 0; j < 8; j++)
#pragma unroll
            for (int q = 0; q < 4; q++) c[i][j][q] = 0.f;
#pragma unroll
    for (int kt = 0; kt < 8; kt++) {
        int kb = kt * 16 + kc;
        uint32_t ah[2][4], al[2][4];
#pragma unroll
        for (int mt = 0; mt < 2; mt++) {
            int mb = warpm + mt * 16 + g8;
            ah[mt][0] = *(const uint32_t*)(Ah + mb * PITCH + kb);
            ah[mt][1] = *(const uint32_t*)(Ah + (mb + 8) * PITCH + kb);
            ah[mt][2] = *(const uint32_t*)(Ah + mb * PITCH + kb + 8);
            ah[mt][3] = *(const uint32_t*)(Ah + (mb + 8) * PITCH + kb + 8);
            al[mt][0] = *(const uint32_t*)(Al + mb * PITCH + kb);
            al[mt][1] = *(const uint32_t*)(Al + (mb + 8) * PITCH + kb);
            al[mt][2] = *(const uint32_t*)(Al + mb * PITCH + kb + 8);
            al[mt][3] = *(const uint32_t*)(Al + (mb + 8) * PITCH + kb + 8);
        }
#pragma unroll
        for (int nt = 0; nt < 8; nt++) {
            int nb = warpn + nt * 8 + g8;
            uint32_t bh0 = *(const uint32_t*)(Bh + nb * PITCH + kb);
            uint32_t bh1 = *(const uint32_t*)(Bh + nb * PITCH + kb + 8);
            uint32_t bl0 = *(const uint32_t*)(Bl + nb * PITCH + kb);
            uint32_t bl1 = *(const uint32_t*)(Bl + nb * PITCH + kb + 8);
#pragma unroll
            for (int mt = 0; mt < 2; mt++) {
                MMA_BF16(c[mt][nt], ah[mt][0], ah[mt][1], ah[mt][2], ah[mt][3], bh0, bh1);
                MMA_BF16(c[mt][nt], ah[mt][0], ah[mt][1], ah[mt][2], ah[mt][3], bl0, bl1);
                MMA_BF16(c[mt][nt], al[mt][0], al[mt][1], al[mt][2], al[mt][3], bh0, bh1);
            }
        }
    }
}

__global__ __launch_bounds__(256) void k_stack2(
    const float* __restrict__ w2a, const float* __restrict__ b2a,
    const float* __restrict__ g2a, const float* __restrict__ be2a,
    const float* __restrict__ w2b, const float* __restrict__ b2b,
    const float* __restrict__ g2b, const float* __restrict__ be2b,
    const float* __restrict__ wl, const float* __restrict__ bl,
    float* __restrict__ out, int out_size)
{
    extern __shared__ __align__(16) __nv_bfloat16 smh[];
    __nv_bfloat16* ANH = smh;                 // 128*PITCH each
    __nv_bfloat16* ANL = smh + 17408;
    __nv_bfloat16* B1H = smh + 34816;         // x2 -> tmpT -> h2
    __nv_bfloat16* B1L = smh + 52224;
    __nv_bfloat16* SCH = smh + 69632;         // w2aT -> w2bT -> tmp2T
    __nv_bfloat16* SCL = smh + 87040;
    __shared__ float red[128], red2[128];
    __shared__ float gv[128];
    __shared__ float lg[10];
    __shared__ float lse;
    int b = blockIdx.x, t = threadIdx.x, lane = t & 31;
    int warpm = ((t >> 5) & 3) * 32, warpn = (t >> 7) * 64;
    int g8 = lane >> 2, kc = (lane & 3) * 2;
    const float INVN = 1.f / (NB * CH);

    // load An, x2, w2aT
    for (int i = t; i < 16384; i += 256) {
        int r = i >> 7, cc = i & 127;
        split1(g_An[b * 16384 + i], ANH[r * PITCH + cc], ANL[r * PITCH + cc]);
        split1(g_x2[b * 16384 + i], B1H[r * PITCH + cc], B1L[r * PITCH + cc]);
        split1(w2a[i], SCH[cc * PITCH + r], SCL[cc * PITCH + r]);   // i = k*128+n -> [n][k]
    }
    __syncthreads();

    float c[2][8][4];

    // G1: tmp = x2 @ w2a
    mma_sm(B1H, B1L, SCH, SCL, c, warpm, warpn, g8, kc);
    __syncthreads();
#pragma unroll
    for (int mt = 0; mt < 2; mt++) {
        int r = warpm + mt * 16 + g8;
#pragma unroll
        for (int nt = 0; nt < 8; nt++) {
            int n = warpn + nt * 8 + kc;
            split1(c[mt][nt][0], B1H[n * PITCH + r],       B1L[n * PITCH + r]);
            split1(c[mt][nt][1], B1H[(n + 1) * PITCH + r], B1L[(n + 1) * PITCH + r]);
            split1(c[mt][nt][2], B1H[n * PITCH + r + 8],       B1L[n * PITCH + r + 8]);
            split1(c[mt][nt][3], B1H[(n + 1) * PITCH + r + 8], B1L[(n + 1) * PITCH + r + 8]);
        }
    }
    __syncthreads();

    // G2: y = An @ tmp (+b2a), stats
    mma_sm(ANH, ANL, B1H, B1L, c, warpm, warpn, g8, kc);
    if (t < 128) { red[t] = 0.f; red2[t] = 0.f; }
    __syncthreads();
#pragma unroll
    for (int nt = 0; nt < 8; nt++) {
        int n = warpn + nt * 8 + kc;
        float b0 = b2a[n], b1 = b2a[n + 1];
        float v00 = c[0][nt][0] + b0, v01 = c[0][nt][1] + b1;
        float v10 = c[0][nt][2] + b0, v11 = c[0][nt][3] + b1;
        float w00 = c[1][nt][0] + b0, w01 = c[1][nt][1] + b1;
        float w10 = c[1][nt][2] + b0, w11 = c[1][nt][3] + b1;
        atomicAdd(&red[n],      v00 + v10 + w00 + w10);
        atomicAdd(&red[n + 1],  v01 + v11 + w01 + w11);
        atomicAdd(&red2[n],     v00 * v00 + v10 * v10 + w00 * w00 + w10 * w10);
        atomicAdd(&red2[n + 1], v01 * v01 + v11 * v11 + w01 * w01 + w11 * w11);
    }
    __syncthreads();
    if (t < 128) { atomicAdd(&g_s2a[t], red[t]); atomicAdd(&g_q2a[t], red2[t]); }

    gridbar(NB);

    // bn + silu -> h2 into BUF1 ([m][k] layout)
    float scv[8][2], shv[8][2];
#pragma unroll
    for (int nt = 0; nt < 8; nt++) {
#pragma unroll
        for (int q = 0; q < 2; q++) {
            int n = warpn + nt * 8 + kc + q;
            float m = g_s2a[n] * INVN;
            float var = g_q2a[n] * INVN - m * m;
            float s = g2a[n] * rsqrtf(var + 1e-5f);
            scv[nt][q] = s; shv[nt][q] = be2a[n] - s * m;
        }
    }
    __syncthreads();   // BUF1 reads in G2 done
#pragma unroll
    for (int mt = 0; mt < 2; mt++) {
        int r = warpm + mt * 16 + g8;
#pragma unroll
        for (int nt = 0; nt < 8; nt++) {
            int n = warpn + nt * 8 + kc;
            float b0 = b2a[n], b1 = b2a[n + 1];
            float a;
            a = scv[nt][0] * (c[mt][nt][0] + b0) + shv[nt][0]; float h00 = a / (1.f + __expf(-a));
            a = scv[nt][1] * (c[mt][nt][1] + b1) + shv[nt][1]; float h01 = a / (1.f + __expf(-a));
            a = scv[nt][0] * (c[mt][nt][2] + b0) + shv[nt][0]; float h10 = a / (1.f + __expf(-a));
            a = scv[nt][1] * (c[mt][nt][3] + b1) + shv[nt][1]; float h11 = a / (1.f + __expf(-a));
            *reinterpret_cast<uint32_t*>(B1H + r * PITCH + n) = pack_hi(h00, h01);
            *reinterpret_cast<uint32_t*>(B1L + r * PITCH + n) = pack_lo(h00, h01);
            *reinterpret_cast<uint32_t*>(B1H + (r + 8) * PITCH + n) = pack_hi(h10, h11);
            *reinterpret_cast<uint32_t*>(B1L + (r + 8) * PITCH + n) = pack_lo(h10, h11);
        }
    }
    // w2bT into SCR
    __syncthreads();
    for (int i = t; i < 16384; i += 256) {
        int k = i >> 7, n = i & 127;
        split1(w2b[i], SCH[n * PITCH + k], SCL[n * PITCH + k]);
    }
    __syncthreads();

    // G3: tmp2 = h2 @ w2b
    mma_sm(B1H, B1L, SCH, SCL, c, warpm, warpn, g8, kc);
    __syncthreads();
#pragma unroll
    for (int mt = 0; mt < 2; mt++) {
        int r = warpm + mt * 16 + g8;
#pragma unroll
        for (int nt = 0; nt < 8; nt++) {
            int n = warpn + nt * 8 + kc;
            split1(c[mt][nt][0], SCH[n * PITCH + r],       SCL[n * PITCH + r]);
            split1(c[mt][nt][1], SCH[(n + 1) * PITCH + r], SCL[(n + 1) * PITCH + r]);
            split1(c[mt][nt][2], SCH[n * PITCH + r + 8],       SCL[n * PITCH + r + 8]);
            split1(c[mt][nt][3], SCH[(n + 1) * PITCH + r + 8], SCL[(n + 1) * PITCH + r + 8]);
        }
    }
    __syncthreads();

    // G4: y2 = An @ tmp2 (+b2b), stats
    mma_sm(ANH, ANL, SCH, SCL, c, warpm, warpn, g8, kc);
    if (t < 128) { red[t] = 0.f; red2[t] = 0.f; }
    __syncthreads();
#pragma unroll
    for (int nt = 0; nt < 8; nt++) {
        int n = warpn + nt * 8 + kc;
        float b0 = b2b[n], b1 = b2b[n + 1];
        float v00 = c[0][nt][0] + b0, v01 = c[0][nt][1] + b1;
        float v10 = c[0][nt][2] + b0, v11 = c[0][nt][3] + b1;
        float w00 = c[1][nt][0] + b0, w01 = c[1][nt][1] + b1;
        float w10 = c[1][nt][2] + b0, w11 = c[1][nt][3] + b1;
        atomicAdd(&red[n],      v00 + v10 + w00 + w10);
        atomicAdd(&red[n + 1],  v01 + v11 + w01 + w11);
        atomicAdd(&red2[n],     v00 * v00 + v10 * v10 + w00 * w00 + w10 * w10);
        atomicAdd(&red2[n + 1], v01 * v01 + v11 * v11 + w01 * w01 + w11 * w11);
    }
    __syncthreads();
    if (t < 128) { atomicAdd(&g_s2b[t], red[t]); atomicAdd(&g_q2b[t], red2[t]); }

    gridbar(2 * NB);

    // h2fin = h2 + silu(bn(y2)); column sums
#pragma unroll
    for (int nt = 0; nt < 8; nt++) {
#pragma unroll
        for (int q = 0; q < 2; q++) {
            int n = warpn + nt * 8 + kc + q;
            float m = g_s2b[n] * INVN;
            float var = g_q2b[n] * INVN - m * m;
            float s = g2b[n] * rsqrtf(var + 1e-5f);
            scv[nt][q] = s; shv[nt][q] = be2b[n] - s * m;
        }
    }
    if (t < 128) red[t] = 0.f;
    __syncthreads();
#pragma unroll
    for (int mt = 0; mt < 2; mt++) {
        int r = warpm + mt * 16 + g8;
#pragma unroll
        for (int nt = 0; nt < 8; nt++) {
            int n = warpn + nt * 8 + kc;
            float b0 = b2b[n], b1 = b2b[n + 1];
            float a;
            a = scv[nt][0] * (c[mt][nt][0] + b0) + shv[nt][0]; float f00 = a / (1.f + __expf(-a));
            a = scv[nt][1] * (c[mt][nt][1] + b1) + shv[nt][1]; float f01 = a / (1.f + __expf(-a));
            a = scv[nt][0] * (c[mt][nt][2] + b0) + shv[nt][0]; float f10 = a / (1.f + __expf(-a));
            a = scv[nt][1] * (c[mt][nt][3] + b1) + shv[nt][1]; float f11 = a / (1.f + __expf(-a));
            f00 += __bfloat162float(B1H[r * PITCH + n]) + __bfloat162float(B1L[r * PITCH + n]);
            f01 += __bfloat162float(B1H[r * PITCH + n + 1]) + __bfloat162float(B1L[r * PITCH + n + 1]);
            f10 += __bfloat162float(B1H[(r + 8) * PITCH + n]) + __bfloat162float(B1L[(r + 8) * PITCH + n]);
            f11 += __bfloat162float(B1H[(r + 8) * PITCH + n + 1]) + __bfloat162float(B1L[(r + 8) * PITCH + n + 1]);
            atomicAdd(&red[n], f00 + f10);
            atomicAdd(&red[n + 1], f01 + f11);
        }
    }
    __syncthreads();
    if (t < 128) gv[t] = red[t] * (1.f / 32.f);
    __syncthreads();
    if (t < 10) {
        float a = bl[t];
        for (int k = 0; k < 128; k++) a += gv[k] * wl[k * 10 + t];
        lg[t] = a;
    }
    __syncthreads();
    if (t == 0) {
        float mx = -1e30f;
        for (int j = 0; j < 10; j++) mx = fmaxf(mx, lg[j]);
        float se = 0.f;
        for (int j = 0; j < 10; j++) se += expf(lg[j] - mx);
        lse = mx + logf(se);
    }
    __syncthreads();
    if (t < 10) {
        int o = b * 10 + t;
        if (o < out_size) out[o] = lg[t] - lse;
    }
    if (b == 0) {
        for (int idx = NB * 10 + t; idx < out_size; idx += 256) out[idx] = 0.f;
    }
}

// ================= host orchestration =================
extern "C" void kernel_launch(void* const* d_in, const int* in_sizes, int n_in,
                              void* d_out, int out_size) {
    const float* x    = (const float*)d_in[0];
    const int*   ei   = (const int*)  d_in[1];
    const float* w1a  = (const float*)d_in[4];
    const float* b1a  = (const float*)d_in[5];
    const float* g1a  = (const float*)d_in[6];
    const float* be1a = (const float*)d_in[7];
    const float* w1b  = (const float*)d_in[8];
    const float* b1b  = (const float*)d_in[9];
    const float* g1b  = (const float*)d_in[10];
    const float* be1b = (const float*)d_in[11];
    const float* wp1  = (const float*)d_in[12];
    const float* bp1  = (const float*)d_in[13];
    const float* w2a  = (const float*)d_in[14];
    const float* b2a  = (const float*)d_in[15];
    const float* g2a  = (const float*)d_in[16];
    const float* be2a = (const float*)d_in[17];
    const float* w2b  = (const float*)d_in[18];
    const float* b2b  = (const float*)d_in[19];
    const float* g2b  = (const float*)d_in[20];
    const float* be2b = (const float*)d_in[21];
    const float* wl   = (const float*)d_in[24];
    const float* bl   = (const float*)d_in[25];
    float* outp = (float*)d_out;
    (void)n_in; (void)in_sizes;

    float *p_lin, *p_y, *p_h, *p_s, *p_xpart, *p_apart;
    float *p_sumA, *p_ssA, *p_sumB, *p_ssB;
    __nv_bfloat16 *p_axh, *p_axl, *p_hah, *p_hal, *p_hbh, *p_hbl;
    __nv_bfloat16 *p_hTh, *p_hTl, *p_sTh, *p_sTl, *p_tTh, *p_tTl;
    __nv_bfloat16 *p_w1ah, *p_w1al, *p_w1bh, *p_w1bl, *p_wp1h, *p_wp1l;
    cudaGetSymbolAddress((void**)&p_lin,   g_lin);
    cudaGetSymbolAddress((void**)&p_y,     g_y);
    cudaGetSymbolAddress((void**)&p_h,     g_h);
    cudaGetSymbolAddress((void**)&p_s,     g_s);
    cudaGetSymbolAddress((void**)&p_xpart, g_xpart);
    cudaGetSymbolAddress((void**)&p_apart, g_apart);
    cudaGetSymbolAddress((void**)&p_sumA,  g_sumA);
    cudaGetSymbolAddress((void**)&p_ssA,   g_ssA);
    cudaGetSymbolAddress((void**)&p_sumB,  g_sumB);
    cudaGetSymbolAddress((void**)&p_ssB,   g_ssB);
    cudaGetSymbolAddress((void**)&p_axh,   g_axh);
    cudaGetSymbolAddress((void**)&p_axl,   g_axl);
    cudaGetSymbolAddress((void**)&p_hah,   g_hah);
    cudaGetSymbolAddress((void**)&p_hal,   g_hal);
    cudaGetSymbolAddress((void**)&p_hbh,   g_hbh);
    cudaGetSymbolAddress((void**)&p_hbl,   g_hbl);
    cudaGetSymbolAddress((void**)&p_hTh,   g_hTh);
    cudaGetSymbolAddress((void**)&p_hTl,   g_hTl);
    cudaGetSymbolAddress((void**)&p_sTh,   g_sTh);
    cudaGetSymbolAddress((void**)&p_sTl,   g_sTl);
    cudaGetSymbolAddress((void**)&p_tTh,   g_tTh);
    cudaGetSymbolAddress((void**)&p_tTl,   g_tTl);
    cudaGetSymbolAddress((void**)&p_w1ah,  g_w1ah);
    cudaGetSymbolAddress((void**)&p_w1al,  g_w1al);
    cudaGetSymbolAddress((void**)&p_w1bh,  g_w1bh);
    cudaGetSymbolAddress((void**)&p_w1bl,  g_w1bl);
    cudaGetSymbolAddress((void**)&p_wp1h,  g_wp1h);
    cudaGetSymbolAddress((void**)&p_wp1l,  g_wp1l);

    static bool attrDone = false;
    if (!attrDone) {
        cudaFuncSetAttribute(k_stack2, cudaFuncAttributeMaxDynamicSharedMemorySize, 208896);
        cudaFuncSetAttribute(k_mma<false, true>,  cudaFuncAttributeMaxDynamicSharedMemorySize, 50176);
        cudaFuncSetAttribute(k_mma<false, false>, cudaFuncAttributeMaxDynamicSharedMemorySize, 50176);
        cudaFuncSetAttribute(k_mma<true, false>,  cudaFuncAttributeMaxDynamicSharedMemorySize, 50176);
        attrDone = true;
    }

    // graph structure (one-pass CSR) + weight split + dinv
    k_zero_deg<<<NNODES / 256, 256>>>();
    k_build<<<NEDGES / 256, 256>>>(ei);
    k_wsplit<<<160, 256>>>(w1a, w1b, wp1);

    // stack 1, layer a
    k_aggx<<<NNODES / 8, 256>>>(x);
    k_mma<false, true><<<256, 256, 50176>>>(p_axh, p_axl, 64,
                                            p_w1ah, p_w1al, nullptr, nullptr, 64,
                                            b1a, p_y, nullptr, 64);
    k_bn<false, true, false><<<dim3(NNODES / 32, 4), 256>>>(
        p_y, nullptr, p_h, p_hah, p_hal, nullptr, nullptr, g1a, be1a, p_sumA, p_ssA);

    // stack 1, layer b (residual)
    k_mma<false, false><<<256, 256, 50176>>>(p_hah, p_hal, 128,
                                             p_w1bh, p_w1bl, nullptr, nullptr, 128,
                                             nullptr, p_lin, nullptr, 128);
    k_aggw<0><<<NNODES / 8, 256>>>(p_lin, b1b, p_y, nullptr, nullptr);
    k_bn<true, false, true><<<dim3(NNODES / 32, 4), 256>>>(
        p_y, p_h, nullptr, p_hbh, p_hbl, p_hTh, p_hTl, g1b, be1b, p_sumB, p_ssB);

    // pooling 1
    k_mma<false, false><<<256, 256, 50176>>>(p_hbh, p_hbl, 128,
                                             p_wp1h, p_wp1l, nullptr, nullptr, 128,
                                             nullptr, p_lin, nullptr, 128);
    k_aggw<1><<<NNODES / 8, 256>>>(p_lin, bp1, p_s, p_sTh, p_sTl);
    k_aggw<2><<<NNODES / 8, 256>>>(p_s, nullptr, nullptr, p_tTh, p_tTl);

    // pooled einsums + reduce/An
    k_mma<true, false><<<dim3(1, 16, NB), 256, 50176>>>(p_sTh, p_sTl, NNODES,
                                                        p_hTh, p_hTl, p_tTh, p_tTl, NNODES,
                                                        nullptr, p_xpart, p_apart, 128);
    k_reduce_an<<<NB, 256>>>();

    // fused stack 2 (mma.sync) + head
    k_stack2<<<NB, 256, 208896>>>(w2a, b2a, g2a, be2a, w2b, b2b, g2b, be2b, wl, bl, outp, out_size);
}

// round 9
// speedup vs baseline: 1.1006x; 1.1006x over previous
#include <cuda_runtime.h>
#include <cuda_bf16.h>
#include <math.h>
#include <stdint.h>

#define NNODES 32768
#define NEDGES 524288
#define NB     32
#define NPG    1024
#define CH     128
#define CIN    64
#define SLOTCAP 64

// ================= helpers =================
__device__ __forceinline__ uint32_t smem_u32(const void* p) {
    uint32_t a;
    asm("{ .reg .u64 t; cvta.to.shared.u64 t, %1; cvt.u32.u64 %0, t; }" : "=r"(a) : "l"(p));
    return a;
}
__device__ __forceinline__ void ffma2(unsigned long long& d, unsigned long long a, unsigned long long b) {
    asm("fma.rn.f32x2 %0, %1, %2, %0;" : "+l"(d) : "l"(a), "l"(b));
}
__device__ __forceinline__ unsigned long long dup_f32(float v) {
    unsigned long long r;
    asm("mov.b64 %0, {%1, %1};" : "=l"(r) : "f"(v));
    return r;
}
__device__ __forceinline__ float2 u2f(unsigned long long v) {
    float2 f;
    asm("mov.b64 {%0, %1}, %2;" : "=f"(f.x), "=f"(f.y) : "l"(v));
    return f;
}
#define CP_ASYNC16(dst, src) asm volatile("cp.async.ca.shared.global [%0], [%1], 16;" :: "r"(dst), "l"(src))
#define CP_COMMIT()          asm volatile("cp.async.commit_group;" ::: "memory")
#define CP_WAIT(n)           asm volatile("cp.async.wait_group %0;" :: "n"(n) : "memory")

#define MMA_BF16(cf, a0, a1, a2, a3, b0, b1) \
    asm volatile("mma.sync.aligned.m16n8k16.row.col.f32.bf16.bf16.f32 " \
        "{%0,%1,%2,%3},{%4,%5,%6,%7},{%8,%9},{%0,%1,%2,%3};" \
        : "+f"((cf)[0]), "+f"((cf)[1]), "+f"((cf)[2]), "+f"((cf)[3]) \
        : "r"(a0), "r"(a1), "r"(a2), "r"(a3), "r"(b0), "r"(b1))

__device__ __forceinline__ uint32_t pack_hi(float a, float b) {
    __nv_bfloat162 h;
    h.x = __float2bfloat16_rn(a); h.y = __float2bfloat16_rn(b);
    return *reinterpret_cast<uint32_t*>(&h);
}
__device__ __forceinline__ uint32_t pack_lo(float a, float b) {
    __nv_bfloat16 ha = __float2bfloat16_rn(a), hb = __float2bfloat16_rn(b);
    __nv_bfloat162 l;
    l.x = __float2bfloat16_rn(a - __bfloat162float(ha));
    l.y = __float2bfloat16_rn(b - __bfloat162float(hb));
    return *reinterpret_cast<uint32_t*>(&l);
}
__device__ __forceinline__ void split1(float v, __nv_bfloat16& h, __nv_bfloat16& l) {
    h = __float2bfloat16_rn(v);
    l = __float2bfloat16_rn(v - __bfloat162float(h));
}

// ================= device scratch =================
__device__ int   g_deg[NNODES];
__device__ int   g_srcbuf[NNODES * SLOTCAP];
__device__ float g_dinv[NNODES];

__device__ float g_lin[NNODES * CH];
__device__ float g_y  [NNODES * CH];
__device__ float g_h  [NNODES * CH];
__device__ float g_s  [NNODES * CH];

__device__ __align__(16) __nv_bfloat16 g_axh[NNODES * CIN], g_axl[NNODES * CIN];
__device__ __align__(16) __nv_bfloat16 g_hah[NNODES * CH],  g_hal[NNODES * CH];
__device__ __align__(16) __nv_bfloat16 g_hbh[NNODES * CH],  g_hbl[NNODES * CH];
__device__ __align__(16) __nv_bfloat16 g_hTh[CH * NNODES],  g_hTl[CH * NNODES];
__device__ __align__(16) __nv_bfloat16 g_sTh[CH * NNODES],  g_sTl[CH * NNODES];
__device__ __align__(16) __nv_bfloat16 g_tTh[CH * NNODES],  g_tTl[CH * NNODES];
__device__ __align__(16) __nv_bfloat16 g_w1ah[CH * CIN], g_w1al[CH * CIN];
__device__ __align__(16) __nv_bfloat16 g_w1bh[CH * CH],  g_w1bl[CH * CH];
__device__ __align__(16) __nv_bfloat16 g_wp1h[CH * CH],  g_wp1l[CH * CH];

__device__ float g_xpart[8 * NB * CH * CH];
__device__ float g_apart[8 * NB * CH * CH];
__device__ float g_x2  [NB * CH * CH];
__device__ float g_A2  [NB * CH * CH];
__device__ float g_An  [NB * CH * CH];

__device__ float g_sumA[CH], g_ssA[CH], g_sumB[CH], g_ssB[CH];
__device__ float g_s2a[CH], g_q2a[CH], g_s2b[CH], g_q2b[CH];
__device__ int   g_bar;

// ================= graph structure (one-pass bucket CSR) =================
__global__ void k_zero_deg() {
    int i = blockIdx.x * 256 + threadIdx.x;
    g_deg[i] = 0;
    if (i < 128) { g_sumA[i] = 0.f; g_ssA[i] = 0.f; g_sumB[i] = 0.f; g_ssB[i] = 0.f; }
}
__global__ void k_build(const int* __restrict__ ei) {
    int e = blockIdx.x * 256 + threadIdx.x;
    if (e < NEDGES) {
        int d = ei[NEDGES + e];
        int p = atomicAdd(&g_deg[d], 1);
        g_srcbuf[d * SLOTCAP + p] = ei[e];
    }
}

// weights transpose + bf16 split; also dinv (after k_build)
__global__ void k_wsplit(const float* __restrict__ w1a, const float* __restrict__ w1b,
                         const float* __restrict__ wp1) {
    int idx = blockIdx.x * 256 + threadIdx.x;      // 160 blocks = 40960
    if (idx < NNODES) g_dinv[idx] = rsqrtf((float)g_deg[idx] + 1.0f);
    if (idx < 8192) {
        int n = idx >> 6, k = idx & 63;
        split1(w1a[k * 128 + n], g_w1ah[idx], g_w1al[idx]);
    } else if (idx < 24576) {
        int j = idx - 8192;
        int n = j >> 7, k = j & 127;
        split1(w1b[k * 128 + n], g_w1bh[j], g_w1bl[j]);
    } else if (idx < 40960) {
        int j = idx - 24576;
        int n = j >> 7, k = j & 127;
        split1(wp1[k * 128 + n], g_wp1h[j], g_wp1l[j]);
    }
}

// ================= bf16-split mma.sync GEMM (stack 1 + pooled) =================
template<bool POOLED, bool STATS>
__global__ __launch_bounds__(256) void k_mma(
    const __nv_bfloat16* __restrict__ Ah, const __nv_bfloat16* __restrict__ Al, long long pA,
    const __nv_bfloat16* __restrict__ B1h, const __nv_bfloat16* __restrict__ B1l,
    const __nv_bfloat16* __restrict__ B2h, const __nv_bfloat16* __restrict__ B2l, long long pB,
    const float* __restrict__ bias, float* __restrict__ C1, float* __restrict__ C2, int K)
{
    extern __shared__ __align__(16) char smem[];
    __nv_bfloat16* SB = reinterpret_cast<__nv_bfloat16*>(smem);
    float* sstat = reinterpret_cast<float*>(smem + 49152);
    int t = threadIdx.x, lane = t & 31;
    int warpm = ((t >> 5) & 3) * 32, warpn = (t >> 7) * 64;

    const __nv_bfloat16 *Ahb, *Alb, *Bhb, *Blb;
    float* Cb;
    if (POOLED) {
        int g = blockIdx.z;
        int half = blockIdx.y >> 3, chunk = blockIdx.y & 7;
        long long ko = (long long)g * 1024 + (long long)chunk * 128;
        Ahb = Ah + ko; Alb = Al + ko;
        Bhb = (half ? B2h : B1h) + ko;
        Blb = (half ? B2l : B1l) + ko;
        Cb = (half ? C2 : C1) + (long long)(chunk * NB + g) * (CH * CH);
    } else {
        long long m0 = (long long)blockIdx.x * 128;
        Ahb = Ah + m0 * pA; Alb = Al + m0 * pA;
        Bhb = B1h; Blb = B1l;
        Cb = C1 + m0 * 128;
    }
    if (STATS) { sstat[t] = 0.f; }

    uint32_t sbase = smem_u32(SB);
    int sr = t >> 1, sc = t & 1;
    uint32_t dofs = sbase + sr * 48 + sc * 16;
    CP_ASYNC16(dofs,         Ahb + (long long)sr * pA + sc * 8);
    CP_ASYNC16(dofs + 6144,  Alb + (long long)sr * pA + sc * 8);
    CP_ASYNC16(dofs + 12288, Bhb + (long long)sr * pB + sc * 8);
    CP_ASYNC16(dofs + 18432, Blb + (long long)sr * pB + sc * 8);
    CP_COMMIT();

    float c[2][8][4];
#pragma unroll
    for (int i = 0; i < 2; i++)
#pragma unroll
        for (int j = 0; j < 8; j++)
#pragma unroll
            for (int q = 0; q < 4; q++) c[i][j][q] = 0.f;

    int g8 = lane >> 2, kc = (lane & 3) * 2;
    int NT = K >> 4;
    for (int kt = 0; kt < NT; kt++) {
        if (kt + 1 < NT) {
            int k0 = (kt + 1) << 4;
            uint32_t d2 = dofs + ((kt + 1) & 1) * 24576;
            CP_ASYNC16(d2,         Ahb + (long long)sr * pA + k0 + sc * 8);
            CP_ASYNC16(d2 + 6144,  Alb + (long long)sr * pA + k0 + sc * 8);
            CP_ASYNC16(d2 + 12288, Bhb + (long long)sr * pB + k0 + sc * 8);
            CP_ASYNC16(d2 + 18432, Blb + (long long)sr * pB + k0 + sc * 8);
            CP_COMMIT();
            CP_WAIT(1);
        } else {
            CP_WAIT(0);
        }
        __syncthreads();
        const __nv_bfloat16* P = SB + (kt & 1) * 12288;
        uint32_t ah[2][4], al[2][4];
#pragma unroll
        for (int mt = 0; mt < 2; mt++) {
            int mb = warpm + mt * 16 + g8;
            ah[mt][0] = *(const uint32_t*)(P + mb * 24 + kc);
            ah[mt][1] = *(const uint32_t*)(P + (mb + 8) * 24 + kc);
            ah[mt][2] = *(const uint32_t*)(P + mb * 24 + kc + 8);
            ah[mt][3] = *(const uint32_t*)(P + (mb + 8) * 24 + kc + 8);
            al[mt][0] = *(const uint32_t*)(P + 3072 + mb * 24 + kc);
            al[mt][1] = *(const uint32_t*)(P + 3072 + (mb + 8) * 24 + kc);
            al[mt][2] = *(const uint32_t*)(P + 3072 + mb * 24 + kc + 8);
            al[mt][3] = *(const uint32_t*)(P + 3072 + (mb + 8) * 24 + kc + 8);
        }
#pragma unroll
        for (int nt = 0; nt < 8; nt++) {
            int nb = warpn + nt * 8 + g8;
            uint32_t bh0 = *(const uint32_t*)(P + 6144 + nb * 24 + kc);
            uint32_t bh1 = *(const uint32_t*)(P + 6144 + nb * 24 + kc + 8);
            uint32_t bl0 = *(const uint32_t*)(P + 9216 + nb * 24 + kc);
            uint32_t bl1 = *(const uint32_t*)(P + 9216 + nb * 24 + kc + 8);
#pragma unroll
            for (int mt = 0; mt < 2; mt++) {
                MMA_BF16(c[mt][nt], ah[mt][0], ah[mt][1], ah[mt][2], ah[mt][3], bh0, bh1);
                MMA_BF16(c[mt][nt], ah[mt][0], ah[mt][1], ah[mt][2], ah[mt][3], bl0, bl1);
                MMA_BF16(c[mt][nt], al[mt][0], al[mt][1], al[mt][2], al[mt][3], bh0, bh1);
            }
        }
        __syncthreads();
    }

    float cs[8][2], cq[8][2];
    if (STATS) {
#pragma unroll
        for (int j = 0; j < 8; j++) { cs[j][0] = cs[j][1] = 0.f; cq[j][0] = cq[j][1] = 0.f; }
    }
#pragma unroll
    for (int mt = 0; mt < 2; mt++) {
        int row = warpm + mt * 16 + g8;
#pragma unroll
        for (int nt = 0; nt < 8; nt++) {
            int col = warpn + nt * 8 + kc;
            float b0 = bias ? bias[col] : 0.f;
            float b1 = bias ? bias[col + 1] : 0.f;
            float v00 = c[mt][nt][0] + b0, v01 = c[mt][nt][1] + b1;
            float v10 = c[mt][nt][2] + b0, v11 = c[mt][nt][3] + b1;
            *reinterpret_cast<float2*>(Cb + (long long)row * 128 + col) = make_float2(v00, v01);
            *reinterpret_cast<float2*>(Cb + (long long)(row + 8) * 128 + col) = make_float2(v10, v11);
            if (STATS) {
                cs[nt][0] += v00 + v10; cq[nt][0] += v00 * v00 + v10 * v10;
                cs[nt][1] += v01 + v11; cq[nt][1] += v01 * v01 + v11 * v11;
            }
        }
    }
    if (STATS) {
        __syncthreads();
#pragma unroll
        for (int nt = 0; nt < 8; nt++) {
            int col = warpn + nt * 8 + kc;
            atomicAdd(&sstat[col], cs[nt][0]);
            atomicAdd(&sstat[col + 1], cs[nt][1]);
            atomicAdd(&sstat[128 + col], cq[nt][0]);
            atomicAdd(&sstat[128 + col + 1], cq[nt][1]);
        }
        __syncthreads();
        if (t < 128) {
            atomicAdd(&g_sumA[t], sstat[t]);
            atomicAdd(&g_ssA[t], sstat[128 + t]);
        }
    }
}

// ================= warp-per-node aggregation =================
template<int MODE>
__global__ __launch_bounds__(256) void k_aggw(
    const float* __restrict__ in, const float* __restrict__ bias, float* __restrict__ out,
    __nv_bfloat16* __restrict__ oTh, __nv_bfloat16* __restrict__ oTl)
{
    __shared__ float sred[8][128];
    __shared__ float st[8][132];
    int t = threadIdx.x, w = t >> 5, lane = t & 31;
    int i = blockIdx.x * 8 + w;
    int e0 = i * SLOTCAP, n = g_deg[i];
    float ax = 0.f, ay = 0.f, az = 0.f, aw = 0.f;
    for (int c0 = 0; c0 < n; c0 += 32) {
        int m = n - c0; if (m > 32) m = 32;
        int src = 0; float dv = 0.f;
        if (lane < m) {
            src = g_srcbuf[e0 + c0 + lane];
            if (MODE != 2) dv = g_dinv[src];
        }
        for (int kk = 0; kk < m; kk++) {
            int s = __shfl_sync(0xffffffffu, src, kk);
            float4 hv = *reinterpret_cast<const float4*>(in + (long long)s * 128 + lane * 4);
            if (MODE == 2) {
                ax += hv.x; ay += hv.y; az += hv.z; aw += hv.w;
            } else {
                float d = __shfl_sync(0xffffffffu, dv, kk);
                ax += d * hv.x; ay += d * hv.y; az += d * hv.z; aw += d * hv.w;
            }
        }
    }
    float vx, vy, vz, vw;
    if (MODE != 2) {
        float di = g_dinv[i];
        float4 hv = *reinterpret_cast<const float4*>(in + (long long)i * 128 + lane * 4);
        vx = di * (ax + di * hv.x) + bias[lane * 4 + 0];
        vy = di * (ay + di * hv.y) + bias[lane * 4 + 1];
        vz = di * (az + di * hv.z) + bias[lane * 4 + 2];
        vw = di * (aw + di * hv.w) + bias[lane * 4 + 3];
    } else {
        vx = ax; vy = ay; vz = az; vw = aw;
    }
    if (MODE == 1) {
        float mx = fmaxf(fmaxf(vx, vy), fmaxf(vz, vw));
#pragma unroll
        for (int o = 16; o; o >>= 1) mx = fmaxf(mx, __shfl_xor_sync(0xffffffffu, mx, o));
        vx = __expf(vx - mx); vy = __expf(vy - mx); vz = __expf(vz - mx); vw = __expf(vw - mx);
        float sm = vx + vy + vz + vw;
#pragma unroll
        for (int o = 16; o; o >>= 1) sm += __shfl_xor_sync(0xffffffffu, sm, o);
        float inv = 1.f / sm;
        vx *= inv; vy *= inv; vz *= inv; vw *= inv;
    }
    if (MODE != 2) {
        float4 o4 = { vx, vy, vz, vw };
        *reinterpret_cast<float4*>(out + (long long)i * 128 + lane * 4) = o4;
    }
    if (MODE == 0) {
        sred[w][lane * 4 + 0] = vx; sred[w][lane * 4 + 1] = vy;
        sred[w][lane * 4 + 2] = vz; sred[w][lane * 4 + 3] = vw;
        __syncthreads();
        if (t < 128) {
            float s = 0.f, q = 0.f;
#pragma unroll
            for (int ww = 0; ww < 8; ww++) { float v = sred[ww][t]; s += v; q += v * v; }
            atomicAdd(&g_sumB[t], s);
            atomicAdd(&g_ssB[t], q);
        }
    } else {
        st[w][lane * 4 + 0] = vx; st[w][lane * 4 + 1] = vy;
        st[w][lane * 4 + 2] = vz; st[w][lane * 4 + 3] = vw;
        __syncthreads();
        if (t < 128) {
            int c = t;
            float v0 = st[0][c], v1 = st[1][c], v2 = st[2][c], v3 = st[3][c];
            float v4 = st[4][c], v5 = st[5][c], v6 = st[6][c], v7 = st[7][c];
            long long o = (long long)c * NNODES + blockIdx.x * 8;
            uint4 hv, lv;
            hv.x = pack_hi(v0, v1); hv.y = pack_hi(v2, v3);
            hv.z = pack_hi(v4, v5); hv.w = pack_hi(v6, v7);
            lv.x = pack_lo(v0, v1); lv.y = pack_lo(v2, v3);
            lv.z = pack_lo(v4, v5); lv.w = pack_lo(v6, v7);
            *reinterpret_cast<uint4*>(oTh + o) = hv;
            *reinterpret_cast<uint4*>(oTl + o) = lv;
        }
    }
}

// agg of x (64 ch) -> row-major bf16 hi/lo
__global__ __launch_bounds__(256) void k_aggx(const float* __restrict__ x) {
    int t = threadIdx.x, w = t >> 5, lane = t & 31;
    int i = blockIdx.x * 8 + w;
    int e0 = i * SLOTCAP, n = g_deg[i];
    float ax = 0.f, ay = 0.f;
    for (int c0 = 0; c0 < n; c0 += 32) {
        int m = n - c0; if (m > 32) m = 32;
        int src = 0; float dv = 0.f;
        if (lane < m) { src = g_srcbuf[e0 + c0 + lane]; dv = g_dinv[src]; }
        for (int kk = 0; kk < m; kk++) {
            int s = __shfl_sync(0xffffffffu, src, kk);
            float d = __shfl_sync(0xffffffffu, dv, kk);
            float2 hv = *reinterpret_cast<const float2*>(x + (long long)s * 64 + lane * 2);
            ax += d * hv.x; ay += d * hv.y;
        }
    }
    float di = g_dinv[i];
    float2 hv = *reinterpret_cast<const float2*>(x + (long long)i * 64 + lane * 2);
    ax = di * (ax + di * hv.x);
    ay = di * (ay + di * hv.y);
    long long o = (long long)i * 64 + lane * 2;
    *reinterpret_cast<uint32_t*>(g_axh + o) = pack_hi(ax, ay);
    *reinterpret_cast<uint32_t*>(g_axl + o) = pack_lo(ax, ay);
}

// ================= BN+SiLU(+res); fp32 h (opt), row bf16, trans bf16 (opt) =================
template<bool RES, bool WH, bool WT>
__global__ __launch_bounds__(256) void k_bn(
    const float* __restrict__ y, const float* __restrict__ res, float* __restrict__ h,
    __nv_bfloat16* __restrict__ rh, __nv_bfloat16* __restrict__ rl,
    __nv_bfloat16* __restrict__ th, __nv_bfloat16* __restrict__ tl,
    const float* __restrict__ gw, const float* __restrict__ be,
    const float* __restrict__ sumArr, const float* __restrict__ ssArr)
{
    __shared__ float tile[32][33];
    __shared__ float sc[32], sh[32];
    int t = threadIdx.x;
    int n0 = blockIdx.x * 32, c0 = blockIdx.y * 32;
    if (t < 32) {
        int c = c0 + t;
        float m = sumArr[c] * (1.f / NNODES);
        float var = ssArr[c] * (1.f / NNODES) - m * m;
        float s = gw[c] * rsqrtf(var + 1e-5f);
        sc[t] = s;
        sh[t] = be[c] - s * m;
    }
    __syncthreads();
    int nl = t >> 3, cg = t & 7;
    long long idx = (long long)(n0 + nl) * 128 + c0 + cg * 4;
    float4 v = *reinterpret_cast<const float4*>(y + idx);
    float o0, o1, o2, o3;
    {
        float a;
        a = sc[cg * 4 + 0] * v.x + sh[cg * 4 + 0]; o0 = a / (1.f + __expf(-a));
        a = sc[cg * 4 + 1] * v.y + sh[cg * 4 + 1]; o1 = a / (1.f + __expf(-a));
        a = sc[cg * 4 + 2] * v.z + sh[cg * 4 + 2]; o2 = a / (1.f + __expf(-a));
        a = sc[cg * 4 + 3] * v.w + sh[cg * 4 + 3]; o3 = a / (1.f + __expf(-a));
    }
    if (RES) {
        float4 r = *reinterpret_cast<const float4*>(res + idx);
        o0 += r.x; o1 += r.y; o2 += r.z; o3 += r.w;
    }
    if (WH) {
        float4 ov = { o0, o1, o2, o3 };
        *reinterpret_cast<float4*>(h + idx) = ov;
    }
    {
        uint2 hv, lv;
        hv.x = pack_hi(o0, o1); hv.y = pack_hi(o2, o3);
        lv.x = pack_lo(o0, o1); lv.y = pack_lo(o2, o3);
        *reinterpret_cast<uint2*>(rh + idx) = hv;
        *reinterpret_cast<uint2*>(rl + idx) = lv;
    }
    if (WT) {
        tile[nl][cg * 4 + 0] = o0; tile[nl][cg * 4 + 1] = o1;
        tile[nl][cg * 4 + 2] = o2; tile[nl][cg * 4 + 3] = o3;
        __syncthreads();
        int cc = t >> 3, g = t & 7;
        float w0 = tile[g * 4 + 0][cc], w1 = tile[g * 4 + 1][cc];
        float w2 = tile[g * 4 + 2][cc], w3 = tile[g * 4 + 3][cc];
        long long o = (long long)(c0 + cc) * NNODES + n0 + g * 4;
        uint2 hv, lv;
        hv.x = pack_hi(w0, w1); hv.y = pack_hi(w2, w3);
        lv.x = pack_lo(w0, w1); lv.y = pack_lo(w2, w3);
        *reinterpret_cast<uint2*>(th + o) = hv;
        *reinterpret_cast<uint2*>(tl + o) = lv;
    }
}

// ================= reduce partials + dinv2 + An; reset stack-2 state =================
__global__ __launch_bounds__(256) void k_reduce_an() {
    int b = blockIdx.x, t = threadIdx.x;
    if (b == 0 && t < 128) {
        g_s2a[t] = 0.f; g_q2a[t] = 0.f; g_s2b[t] = 0.f; g_q2b[t] = 0.f;
        if (t == 0) g_bar = 0;
    }
    const long long PS = (long long)NB * CH * CH;
    const long long BO = (long long)b * CH * CH;
    __shared__ float sd[128];
    for (int idx = t; idx < CH * CH; idx += 256) {
        float s = 0.f;
#pragma unroll
        for (int p = 0; p < 8; p++) s += g_xpart[p * PS + BO + idx];
        g_x2[BO + idx] = s;
    }
    int w = t >> 5, lane = t & 31;
    for (int r = w; r < 128; r += 8) {
        float rsum = 0.f;
#pragma unroll
        for (int q = 0; q < 4; q++) {
            int idx = r * 128 + lane + q * 32;
            float s = 0.f;
#pragma unroll
            for (int p = 0; p < 8; p++) s += g_apart[p * PS + BO + idx];
            g_A2[BO + idx] = s;
            rsum += s;
        }
#pragma unroll
        for (int o = 16; o; o >>= 1) rsum += __shfl_down_sync(0xffffffffu, rsum, o);
        if (lane == 0) sd[r] = rsqrtf(rsum + 1.0f);
    }
    __syncthreads();
    for (int idx = t; idx < CH * CH; idx += 256) {
        int i = idx >> 7, j = idx & 127;
        float v = g_A2[BO + idx] + (i == j ? 1.f : 0.f);
        g_An[BO + idx] = sd[i] * v * sd[j];
    }
}

// ================= fused stack-2 (FFMA2, 32 blocks, grid barrier) =================
__device__ __forceinline__ void gridbar(int target) {
    __syncthreads();
    __threadfence();
    if (threadIdx.x == 0) {
        atomicAdd(&g_bar, 1);
        while (*(volatile int*)&g_bar < target) __nanosleep(64);
    }
    __syncthreads();
    __threadfence();
}

__device__ __forceinline__ void gemm_sm128(const float* __restrict__ P, const float* __restrict__ Q,
                                           unsigned long long acc2[8][4], int tx, int ty)
{
#pragma unroll
    for (int i = 0; i < 8; i++)
#pragma unroll
        for (int j = 0; j < 4; j++) acc2[i][j] = 0ull;
#pragma unroll 2
    for (int k = 0; k < 128; k++) {
        float a[8];
#pragma unroll
        for (int i = 0; i < 8; i++) a[i] = P[(ty * 8 + i) * 128 + k];
        const unsigned long long* Qp =
            reinterpret_cast<const unsigned long long*>(&Q[k * 128 + tx * 8]);
        unsigned long long b0 = Qp[0], b1 = Qp[1], b2 = Qp[2], b3 = Qp[3];
#pragma unroll
        for (int i = 0; i < 8; i++) {
            unsigned long long ad = dup_f32(a[i]);
            ffma2(acc2[i][0], ad, b0);
            ffma2(acc2[i][1], ad, b1);
            ffma2(acc2[i][2], ad, b2);
            ffma2(acc2[i][3], ad, b3);
        }
    }
}

__global__ __launch_bounds__(256) void k_stack2(
    const float* __restrict__ w2a, const float* __restrict__ b2a,
    const float* __restrict__ g2a, const float* __restrict__ be2a,
    const float* __restrict__ w2b, const float* __restrict__ b2b,
    const float* __restrict__ g2b, const float* __restrict__ be2b,
    const float* __restrict__ wl, const float* __restrict__ bl,
    float* __restrict__ out, int out_size)
{
    extern __shared__ __align__(16) float sm2[];
    float* AN = sm2;
    float* XB = sm2 + 16384;
    float* WB = sm2 + 32768;
    __shared__ float red[2048];
    __shared__ float gv[128];
    __shared__ float lg[10];
    __shared__ float lse;
    int b = blockIdx.x, t = threadIdx.x, tx = t & 15, ty = t >> 4;
    const float INVN = 1.f / (NB * CH);

    {
        const float4* pAn = (const float4*)(g_An + (long long)b * 16384);
        const float4* pX2 = (const float4*)(g_x2 + (long long)b * 16384);
        const float4* pWa = (const float4*)w2a;
        float4* An4 = (float4*)AN; float4* X4 = (float4*)XB; float4* W4 = (float4*)WB;
        for (int i = t; i < 4096; i += 256) { An4[i] = pAn[i]; X4[i] = pX2[i]; W4[i] = pWa[i]; }
    }
    __syncthreads();

    unsigned long long acc2[8][4];
    float cs[8], cq[8];

    gemm_sm128(XB, WB, acc2, tx, ty);
    __syncthreads();
#pragma unroll
    for (int i = 0; i < 8; i++)
#pragma unroll
        for (int j = 0; j < 4; j++) {
            float2 p = u2f(acc2[i][j]);
            XB[(ty * 8 + i) * 128 + tx * 8 + 2 * j] = p.x;
            XB[(ty * 8 + i) * 128 + tx * 8 + 2 * j + 1] = p.y;
        }
    __syncthreads();

    gemm_sm128(AN, XB, acc2, tx, ty);
    __syncthreads();
#pragma unroll
    for (int j = 0; j < 8; j++) { cs[j] = 0.f; cq[j] = 0.f; }
#pragma unroll
    for (int i = 0; i < 8; i++)
#pragma unroll
        for (int j = 0; j < 4; j++) {
            float2 p = u2f(acc2[i][j]);
            float v0 = p.x + b2a[tx * 8 + 2 * j];
            float v1 = p.y + b2a[tx * 8 + 2 * j + 1];
            WB[(ty * 8 + i) * 128 + tx * 8 + 2 * j] = v0;
            WB[(ty * 8 + i) * 128 + tx * 8 + 2 * j + 1] = v1;
            cs[2 * j] += v0; cq[2 * j] += v0 * v0;
            cs[2 * j + 1] += v1; cq[2 * j + 1] += v1 * v1;
        }
#pragma unroll
    for (int j = 0; j < 8; j++) red[ty * 128 + tx * 8 + j] = cs[j];
    __syncthreads();
    if (t < 128) { float s = 0.f; for (int g = 0; g < 16; g++) s += red[g * 128 + t]; atomicAdd(&g_s2a[t], s); }
    __syncthreads();
#pragma unroll
    for (int j = 0; j < 8; j++) red[ty * 128 + tx * 8 + j] = cq[j];
    __syncthreads();
    if (t < 128) { float s = 0.f; for (int g = 0; g < 16; g++) s += red[g * 128 + t]; atomicAdd(&g_q2a[t], s); }

    gridbar(NB);

    float scv[8], shv[8];
#pragma unroll
    for (int j = 0; j < 8; j++) {
        int c = tx * 8 + j;
        float m = g_s2a[c] * INVN;
        float var = g_q2a[c] * INVN - m * m;
        float s = g2a[c] * rsqrtf(var + 1e-5f);
        scv[j] = s; shv[j] = be2a[c] - s * m;
    }
#pragma unroll
    for (int i = 0; i < 8; i++)
#pragma unroll
        for (int j = 0; j < 8; j++) {
            float v = WB[(ty * 8 + i) * 128 + tx * 8 + j];
            v = scv[j] * v + shv[j];
            v = v / (1.f + __expf(-v));
            XB[(ty * 8 + i) * 128 + tx * 8 + j] = v;
        }
    __syncthreads();

    {
        const float4* pWb = (const float4*)w2b;
        float4* W4 = (float4*)WB;
        for (int i = t; i < 4096; i += 256) W4[i] = pWb[i];
    }
    __syncthreads();

    gemm_sm128(XB, WB, acc2, tx, ty);
    __syncthreads();
#pragma unroll
    for (int i = 0; i < 8; i++)
#pragma unroll
        for (int j = 0; j < 4; j++) {
            float2 p = u2f(acc2[i][j]);
            WB[(ty * 8 + i) * 128 + tx * 8 + 2 * j] = p.x;
            WB[(ty * 8 + i) * 128 + tx * 8 + 2 * j + 1] = p.y;
        }
    __syncthreads();

    gemm_sm128(AN, WB, acc2, tx, ty);
#pragma unroll
    for (int j = 0; j < 8; j++) { cs[j] = 0.f; cq[j] = 0.f; }
#pragma unroll
    for (int i = 0; i < 8; i++)
#pragma unroll
        for (int j = 0; j < 4; j++) {
            float2 p = u2f(acc2[i][j]);
            float v0 = p.x + b2b[tx * 8 + 2 * j];
            float v1 = p.y + b2b[tx * 8 + 2 * j + 1];
            cs[2 * j] += v0; cq[2 * j] += v0 * v0;
            cs[2 * j + 1] += v1; cq[2 * j + 1] += v1 * v1;
        }
    __syncthreads();
#pragma unroll
    for (int j = 0; j < 8; j++) red[ty * 128 + tx * 8 + j] = cs[j];
    __syncthreads();
    if (t < 128) { float s = 0.f; for (int g = 0; g < 16; g++) s += red[g * 128 + t]; atomicAdd(&g_s2b[t], s); }
    __syncthreads();
#pragma unroll
    for (int j = 0; j < 8; j++) red[ty * 128 + tx * 8 + j] = cq[j];
    __syncthreads();
    if (t < 128) { float s = 0.f; for (int g = 0; g < 16; g++) s += red[g * 128 + t]; atomicAdd(&g_q2b[t], s); }

    gridbar(2 * NB);

#pragma unroll
    for (int j = 0; j < 8; j++) {
        int c = tx * 8 + j;
        float m = g_s2b[c] * INVN;
        float var = g_q2b[c] * INVN - m * m;
        float s = g2b[c] * rsqrtf(var + 1e-5f);
        scv[j] = s; shv[j] = be2b[c] - s * m;
    }
    float colsum[8];
#pragma unroll
    for (int j = 0; j < 8; j++) colsum[j] = 0.f;
#pragma unroll
    for (int i = 0; i < 8; i++)
#pragma unroll
        for (int j = 0; j < 4; j++) {
            float2 p = u2f(acc2[i][j]);
            float v0 = scv[2 * j] * (p.x + b2b[tx * 8 + 2 * j]) + shv[2 * j];
            float v1 = scv[2 * j + 1] * (p.y + b2b[tx * 8 + 2 * j + 1]) + shv[2 * j + 1];
            v0 = v0 / (1.f + __expf(-v0));
            v1 = v1 / (1.f + __expf(-v1));
            v0 += XB[(ty * 8 + i) * 128 + tx * 8 + 2 * j];
            v1 += XB[(ty * 8 + i) * 128 + tx * 8 + 2 * j + 1];
            colsum[2 * j] += v0;
            colsum[2 * j + 1] += v1;
        }
    __syncthreads();
#pragma unroll
    for (int j = 0; j < 8; j++) red[ty * 128 + tx * 8 + j] = colsum[j];
    __syncthreads();
    if (t < 128) {
        float s = 0.f;
        for (int g = 0; g < 16; g++) s += red[g * 128 + t];
        gv[t] = s * (1.f / 32.f);
    }
    __syncthreads();
    if (t < 10) {
        float a = bl[t];
        for (int k = 0; k < 128; k++) a += gv[k] * wl[k * 10 + t];
        lg[t] = a;
    }
    __syncthreads();
    if (t == 0) {
        float mx = -1e30f;
        for (int j = 0; j < 10; j++) mx = fmaxf(mx, lg[j]);
        float se = 0.f;
        for (int j = 0; j < 10; j++) se += expf(lg[j] - mx);
        lse = mx + logf(se);
    }
    __syncthreads();
    if (t < 10) {
        int o = b * 10 + t;
        if (o < out_size) out[o] = lg[t] - lse;
    }
    if (b == 0) {
        for (int idx = NB * 10 + t; idx < out_size; idx += 256) out[idx] = 0.f;
    }
}

// ================= host orchestration =================
extern "C" void kernel_launch(void* const* d_in, const int* in_sizes, int n_in,
                              void* d_out, int out_size) {
    const float* x    = (const float*)d_in[0];
    const int*   ei   = (const int*)  d_in[1];
    const float* w1a  = (const float*)d_in[4];
    const float* b1a  = (const float*)d_in[5];
    const float* g1a  = (const float*)d_in[6];
    const float* be1a = (const float*)d_in[7];
    const float* w1b  = (const float*)d_in[8];
    const float* b1b  = (const float*)d_in[9];
    const float* g1b  = (const float*)d_in[10];
    const float* be1b = (const float*)d_in[11];
    const float* wp1  = (const float*)d_in[12];
    const float* bp1  = (const float*)d_in[13];
    const float* w2a  = (const float*)d_in[14];
    const float* b2a  = (const float*)d_in[15];
    const float* g2a  = (const float*)d_in[16];
    const float* be2a = (const float*)d_in[17];
    const float* w2b  = (const float*)d_in[18];
    const float* b2b  = (const float*)d_in[19];
    const float* g2b  = (const float*)d_in[20];
    const float* be2b = (const float*)d_in[21];
    const float* wl   = (const float*)d_in[24];
    const float* bl   = (const float*)d_in[25];
    float* outp = (float*)d_out;
    (void)n_in; (void)in_sizes;

    float *p_lin, *p_y, *p_h, *p_s, *p_xpart, *p_apart;
    float *p_sumA, *p_ssA, *p_sumB, *p_ssB;
    __nv_bfloat16 *p_axh, *p_axl, *p_hah, *p_hal, *p_hbh, *p_hbl;
    __nv_bfloat16 *p_hTh, *p_hTl, *p_sTh, *p_sTl, *p_tTh, *p_tTl;
    __nv_bfloat16 *p_w1ah, *p_w1al, *p_w1bh, *p_w1bl, *p_wp1h, *p_wp1l;
    cudaGetSymbolAddress((void**)&p_lin,   g_lin);
    cudaGetSymbolAddress((void**)&p_y,     g_y);
    cudaGetSymbolAddress((void**)&p_h,     g_h);
    cudaGetSymbolAddress((void**)&p_s,     g_s);
    cudaGetSymbolAddress((void**)&p_xpart, g_xpart);
    cudaGetSymbolAddress((void**)&p_apart, g_apart);
    cudaGetSymbolAddress((void**)&p_sumA,  g_sumA);
    cudaGetSymbolAddress((void**)&p_ssA,   g_ssA);
    cudaGetSymbolAddress((void**)&p_sumB,  g_sumB);
    cudaGetSymbolAddress((void**)&p_ssB,   g_ssB);
    cudaGetSymbolAddress((void**)&p_axh,   g_axh);
    cudaGetSymbolAddress((void**)&p_axl,   g_axl);
    cudaGetSymbolAddress((void**)&p_hah,   g_hah);
    cudaGetSymbolAddress((void**)&p_hal,   g_hal);
    cudaGetSymbolAddress((void**)&p_hbh,   g_hbh);
    cudaGetSymbolAddress((void**)&p_hbl,   g_hbl);
    cudaGetSymbolAddress((void**)&p_hTh,   g_hTh);
    cudaGetSymbolAddress((void**)&p_hTl,   g_hTl);
    cudaGetSymbolAddress((void**)&p_sTh,   g_sTh);
    cudaGetSymbolAddress((void**)&p_sTl,   g_sTl);
    cudaGetSymbolAddress((void**)&p_tTh,   g_tTh);
    cudaGetSymbolAddress((void**)&p_tTl,   g_tTl);
    cudaGetSymbolAddress((void**)&p_w1ah,  g_w1ah);
    cudaGetSymbolAddress((void**)&p_w1al,  g_w1al);
    cudaGetSymbolAddress((void**)&p_w1bh,  g_w1bh);
    cudaGetSymbolAddress((void**)&p_w1bl,  g_w1bl);
    cudaGetSymbolAddress((void**)&p_wp1h,  g_wp1h);
    cudaGetSymbolAddress((void**)&p_wp1l,  g_wp1l);

    static bool attrDone = false;
    if (!attrDone) {
        cudaFuncSetAttribute(k_stack2, cudaFuncAttributeMaxDynamicSharedMemorySize, 196608);
        cudaFuncSetAttribute(k_mma<false, true>,  cudaFuncAttributeMaxDynamicSharedMemorySize, 50176);
        cudaFuncSetAttribute(k_mma<false, false>, cudaFuncAttributeMaxDynamicSharedMemorySize, 50176);
        cudaFuncSetAttribute(k_mma<true, false>,  cudaFuncAttributeMaxDynamicSharedMemorySize, 50176);
        attrDone = true;
    }

    // graph structure (one-pass CSR) + weight split + dinv
    k_zero_deg<<<NNODES / 256, 256>>>();
    k_build<<<NEDGES / 256, 256>>>(ei);
    k_wsplit<<<160, 256>>>(w1a, w1b, wp1);

    // stack 1, layer a
    k_aggx<<<NNODES / 8, 256>>>(x);
    k_mma<false, true><<<256, 256, 50176>>>(p_axh, p_axl, 64,
                                            p_w1ah, p_w1al, nullptr, nullptr, 64,
                                            b1a, p_y, nullptr, 64);
    k_bn<false, true, false><<<dim3(NNODES / 32, 4), 256>>>(
        p_y, nullptr, p_h, p_hah, p_hal, nullptr, nullptr, g1a, be1a, p_sumA, p_ssA);

    // stack 1, layer b (residual)
    k_mma<false, false><<<256, 256, 50176>>>(p_hah, p_hal, 128,
                                             p_w1bh, p_w1bl, nullptr, nullptr, 128,
                                             nullptr, p_lin, nullptr, 128);
    k_aggw<0><<<NNODES / 8, 256>>>(p_lin, b1b, p_y, nullptr, nullptr);
    k_bn<true, false, true><<<dim3(NNODES / 32, 4), 256>>>(
        p_y, p_h, nullptr, p_hbh, p_hbl, p_hTh, p_hTl, g1b, be1b, p_sumB, p_ssB);

    // pooling 1
    k_mma<false, false><<<256, 256, 50176>>>(p_hbh, p_hbl, 128,
                                             p_wp1h, p_wp1l, nullptr, nullptr, 128,
                                             nullptr, p_lin, nullptr, 128);
    k_aggw<1><<<NNODES / 8, 256>>>(p_lin, bp1, p_s, p_sTh, p_sTl);
    k_aggw<2><<<NNODES / 8, 256>>>(p_s, nullptr, nullptr, p_tTh, p_tTl);

    // pooled einsums + reduce/An
    k_mma<true, false><<<dim3(1, 16, NB), 256, 50176>>>(p_sTh, p_sTl, NNODES,
                                                        p_hTh, p_hTl, p_tTh, p_tTl, NNODES,
                                                        nullptr, p_xpart, p_apart, 128);
    k_reduce_an<<<NB, 256>>>();

    // fused stack 2 (FFMA2) + head
    k_stack2<<<NB, 256, 196608>>>(w2a, b2a, g2a, be2a, w2b, b2b, g2b, be2b, wl, bl, outp, out_size);
}

// round 10
// speedup vs baseline: 1.1056x; 1.0045x over previous
#include <cuda_runtime.h>
#include <cuda_bf16.h>
#include <math.h>
#include <stdint.h>

#define NNODES 32768
#define NEDGES 524288
#define NB     32
#define NPG    1024
#define CH     128
#define CIN    64
#define SLOTCAP 72

// ================= helpers =================
__device__ __forceinline__ uint32_t smem_u32(const void* p) {
    uint32_t a;
    asm("{ .reg .u64 t; cvta.to.shared.u64 t, %1; cvt.u32.u64 %0, t; }" : "=r"(a) : "l"(p));
    return a;
}
__device__ __forceinline__ void ffma2(unsigned long long& d, unsigned long long a, unsigned long long b) {
    asm("fma.rn.f32x2 %0, %1, %2, %0;" : "+l"(d) : "l"(a), "l"(b));
}
__device__ __forceinline__ unsigned long long dup_f32(float v) {
    unsigned long long r;
    asm("mov.b64 %0, {%1, %1};" : "=l"(r) : "f"(v));
    return r;
}
__device__ __forceinline__ float2 u2f(unsigned long long v) {
    float2 f;
    asm("mov.b64 {%0, %1}, %2;" : "=f"(f.x), "=f"(f.y) : "l"(v));
    return f;
}
#define CP_ASYNC16(dst, src) asm volatile("cp.async.ca.shared.global [%0], [%1], 16;" :: "r"(dst), "l"(src))
#define CP_COMMIT()          asm volatile("cp.async.commit_group;" ::: "memory")
#define CP_WAIT(n)           asm volatile("cp.async.wait_group %0;" :: "n"(n) : "memory")

#define MMA_BF16(cf, a0, a1, a2, a3, b0, b1) \
    asm volatile("mma.sync.aligned.m16n8k16.row.col.f32.bf16.bf16.f32 " \
        "{%0,%1,%2,%3},{%4,%5,%6,%7},{%8,%9},{%0,%1,%2,%3};" \
        : "+f"((cf)[0]), "+f"((cf)[1]), "+f"((cf)[2]), "+f"((cf)[3]) \
        : "r"(a0), "r"(a1), "r"(a2), "r"(a3), "r"(b0), "r"(b1))

__device__ __forceinline__ uint32_t pack_hi(float a, float b) {
    __nv_bfloat162 h;
    h.x = __float2bfloat16_rn(a); h.y = __float2bfloat16_rn(b);
    return *reinterpret_cast<uint32_t*>(&h);
}
__device__ __forceinline__ uint32_t pack_lo(float a, float b) {
    __nv_bfloat16 ha = __float2bfloat16_rn(a), hb = __float2bfloat16_rn(b);
    __nv_bfloat162 l;
    l.x = __float2bfloat16_rn(a - __bfloat162float(ha));
    l.y = __float2bfloat16_rn(b - __bfloat162float(hb));
    return *reinterpret_cast<uint32_t*>(&l);
}
__device__ __forceinline__ void split1(float v, __nv_bfloat16& h, __nv_bfloat16& l) {
    h = __float2bfloat16_rn(v);
    l = __float2bfloat16_rn(v - __bfloat162float(h));
}

// ================= device scratch =================
// Gather sources have 8 extra rows; row NNODES is never written => stays zero
// (sentinel target for padded CSR slots).
__device__ int   g_deg[NNODES];
__device__ int   g_srcbuf[NNODES * SLOTCAP];
__device__ float g_dinv[NNODES];

__device__ float g_xs [(NNODES + 8) * CIN];   // dinv-prescaled x
__device__ float g_lin[(NNODES + 8) * CH];    // dinv-prescaled GEMM out
__device__ float g_s  [(NNODES + 8) * CH];
__device__ float g_y  [NNODES * CH];
__device__ float g_h  [NNODES * CH];

__device__ __align__(16) __nv_bfloat16 g_axh[NNODES * CIN], g_axl[NNODES * CIN];
__device__ __align__(16) __nv_bfloat16 g_hah[NNODES * CH],  g_hal[NNODES * CH];
__device__ __align__(16) __nv_bfloat16 g_hbh[NNODES * CH],  g_hbl[NNODES * CH];
__device__ __align__(16) __nv_bfloat16 g_hTh[CH * NNODES],  g_hTl[CH * NNODES];
__device__ __align__(16) __nv_bfloat16 g_sTh[CH * NNODES],  g_sTl[CH * NNODES];
__device__ __align__(16) __nv_bfloat16 g_tTh[CH * NNODES],  g_tTl[CH * NNODES];
__device__ __align__(16) __nv_bfloat16 g_w1ah[CH * CIN], g_w1al[CH * CIN];
__device__ __align__(16) __nv_bfloat16 g_w1bh[CH * CH],  g_w1bl[CH * CH];
__device__ __align__(16) __nv_bfloat16 g_wp1h[CH * CH],  g_wp1l[CH * CH];

__device__ float g_xpart[8 * NB * CH * CH];
__device__ float g_apart[8 * NB * CH * CH];
__device__ float g_x2  [NB * CH * CH];
__device__ float g_A2  [NB * CH * CH];
__device__ float g_An  [NB * CH * CH];

__device__ float g_sumA[CH], g_ssA[CH], g_sumB[CH], g_ssB[CH];
__device__ float g_s2a[CH], g_q2a[CH], g_s2b[CH], g_q2b[CH];
__device__ int   g_bar;

// ================= graph structure (one-pass bucket CSR) =================
__global__ void k_zero_deg() {
    int i = blockIdx.x * 256 + threadIdx.x;
    g_deg[i] = 0;
    if (i < 128) { g_sumA[i] = 0.f; g_ssA[i] = 0.f; g_sumB[i] = 0.f; g_ssB[i] = 0.f; }
}
__global__ void k_build(const int* __restrict__ ei) {
    int e = blockIdx.x * 256 + threadIdx.x;
    if (e < NEDGES) {
        int d = ei[NEDGES + e];
        int p = atomicAdd(&g_deg[d], 1);
        g_srcbuf[d * SLOTCAP + p] = ei[e];
    }
}

// weights transpose + bf16 split; dinv; sentinel-pad buckets to multiple of 8
__global__ void k_wsplit(const float* __restrict__ w1a, const float* __restrict__ w1b,
                         const float* __restrict__ wp1) {
    int idx = blockIdx.x * 256 + threadIdx.x;      // 160 blocks = 40960
    if (idx < NNODES) {
        int deg = g_deg[idx];
        g_dinv[idx] = rsqrtf((float)deg + 1.0f);
        int npad = (deg + 7) & ~7;
        if (npad > SLOTCAP) npad = SLOTCAP;
        for (int p = deg; p < npad; p++) g_srcbuf[idx * SLOTCAP + p] = NNODES;
    }
    if (idx < 8192) {
        int n = idx >> 6, k = idx & 63;
        split1(w1a[k * 128 + n], g_w1ah[idx], g_w1al[idx]);
    } else if (idx < 24576) {
        int j = idx - 8192;
        int n = j >> 7, k = j & 127;
        split1(w1b[k * 128 + n], g_w1bh[j], g_w1bl[j]);
    } else if (idx < 40960) {
        int j = idx - 24576;
        int n = j >> 7, k = j & 127;
        split1(wp1[k * 128 + n], g_wp1h[j], g_wp1l[j]);
    }
}

// prescale x by dinv -> g_xs
__global__ __launch_bounds__(256) void k_xscale(const float* __restrict__ x) {
    int t = blockIdx.x * 256 + threadIdx.x;        // NNODES*32 threads
    int row = t >> 5, c2 = (t & 31) * 2;
    float d = g_dinv[row];
    float2 v = *reinterpret_cast<const float2*>(x + (long long)row * 64 + c2);
    v.x *= d; v.y *= d;
    *reinterpret_cast<float2*>(g_xs + (long long)row * 64 + c2) = v;
}

// ================= bf16-split mma.sync GEMM =================
template<bool POOLED, bool STATS>
__global__ __launch_bounds__(256) void k_mma(
    const __nv_bfloat16* __restrict__ Ah, const __nv_bfloat16* __restrict__ Al, long long pA,
    const __nv_bfloat16* __restrict__ B1h, const __nv_bfloat16* __restrict__ B1l,
    const __nv_bfloat16* __restrict__ B2h, const __nv_bfloat16* __restrict__ B2l, long long pB,
    const float* __restrict__ bias, const float* __restrict__ rowscale,
    float* __restrict__ C1, float* __restrict__ C2, int K)
{
    extern __shared__ __align__(16) char smem[];
    __nv_bfloat16* SB = reinterpret_cast<__nv_bfloat16*>(smem);
    float* sstat = reinterpret_cast<float*>(smem + 49152);
    int t = threadIdx.x, lane = t & 31;
    int warpm = ((t >> 5) & 3) * 32, warpn = (t >> 7) * 64;

    const __nv_bfloat16 *Ahb, *Alb, *Bhb, *Blb;
    float* Cb;
    long long m0 = 0;
    if (POOLED) {
        int g = blockIdx.z;
        int half = blockIdx.y >> 3, chunk = blockIdx.y & 7;
        long long ko = (long long)g * 1024 + (long long)chunk * 128;
        Ahb = Ah + ko; Alb = Al + ko;
        Bhb = (half ? B2h : B1h) + ko;
        Blb = (half ? B2l : B1l) + ko;
        Cb = (half ? C2 : C1) + (long long)(chunk * NB + g) * (CH * CH);
    } else {
        m0 = (long long)blockIdx.x * 128;
        Ahb = Ah + m0 * pA; Alb = Al + m0 * pA;
        Bhb = B1h; Blb = B1l;
        Cb = C1 + m0 * 128;
    }
    if (STATS) { sstat[t] = 0.f; }

    uint32_t sbase = smem_u32(SB);
    int sr = t >> 1, sc = t & 1;
    uint32_t dofs = sbase + sr * 48 + sc * 16;
    CP_ASYNC16(dofs,         Ahb + (long long)sr * pA + sc * 8);
    CP_ASYNC16(dofs + 6144,  Alb + (long long)sr * pA + sc * 8);
    CP_ASYNC16(dofs + 12288, Bhb + (long long)sr * pB + sc * 8);
    CP_ASYNC16(dofs + 18432, Blb + (long long)sr * pB + sc * 8);
    CP_COMMIT();

    float c[2][8][4];
#pragma unroll
    for (int i = 0; i < 2; i++)
#pragma unroll
        for (int j = 0; j < 8; j++)
#pragma unroll
            for (int q = 0; q < 4; q++) c[i][j][q] = 0.f;

    int g8 = lane >> 2, kc = (lane & 3) * 2;
    int NT = K >> 4;
    for (int kt = 0; kt < NT; kt++) {
        if (kt + 1 < NT) {
            int k0 = (kt + 1) << 4;
            uint32_t d2 = dofs + ((kt + 1) & 1) * 24576;
            CP_ASYNC16(d2,         Ahb + (long long)sr * pA + k0 + sc * 8);
            CP_ASYNC16(d2 + 6144,  Alb + (long long)sr * pA + k0 + sc * 8);
            CP_ASYNC16(d2 + 12288, Bhb + (long long)sr * pB + k0 + sc * 8);
            CP_ASYNC16(d2 + 18432, Blb + (long long)sr * pB + k0 + sc * 8);
            CP_COMMIT();
            CP_WAIT(1);
        } else {
            CP_WAIT(0);
        }
        __syncthreads();
        const __nv_bfloat16* P = SB + (kt & 1) * 12288;
        uint32_t ah[2][4], al[2][4];
#pragma unroll
        for (int mt = 0; mt < 2; mt++) {
            int mb = warpm + mt * 16 + g8;
            ah[mt][0] = *(const uint32_t*)(P + mb * 24 + kc);
            ah[mt][1] = *(const uint32_t*)(P + (mb + 8) * 24 + kc);
            ah[mt][2] = *(const uint32_t*)(P + mb * 24 + kc + 8);
            ah[mt][3] = *(const uint32_t*)(P + (mb + 8) * 24 + kc + 8);
            al[mt][0] = *(const uint32_t*)(P + 3072 + mb * 24 + kc);
            al[mt][1] = *(const uint32_t*)(P + 3072 + (mb + 8) * 24 + kc);
            al[mt][2] = *(const uint32_t*)(P + 3072 + mb * 24 + kc + 8);
            al[mt][3] = *(const uint32_t*)(P + 3072 + (mb + 8) * 24 + kc + 8);
        }
#pragma unroll
        for (int nt = 0; nt < 8; nt++) {
            int nb = warpn + nt * 8 + g8;
            uint32_t bh0 = *(const uint32_t*)(P + 6144 + nb * 24 + kc);
            uint32_t bh1 = *(const uint32_t*)(P + 6144 + nb * 24 + kc + 8);
            uint32_t bl0 = *(const uint32_t*)(P + 9216 + nb * 24 + kc);
            uint32_t bl1 = *(const uint32_t*)(P + 9216 + nb * 24 + kc + 8);
#pragma unroll
            for (int mt = 0; mt < 2; mt++) {
                MMA_BF16(c[mt][nt], ah[mt][0], ah[mt][1], ah[mt][2], ah[mt][3], bh0, bh1);
                MMA_BF16(c[mt][nt], ah[mt][0], ah[mt][1], ah[mt][2], ah[mt][3], bl0, bl1);
                MMA_BF16(c[mt][nt], al[mt][0], al[mt][1], al[mt][2], al[mt][3], bh0, bh1);
            }
        }
        __syncthreads();
    }

    float cs[8][2], cq[8][2];
    if (STATS) {
#pragma unroll
        for (int j = 0; j < 8; j++) { cs[j][0] = cs[j][1] = 0.f; cq[j][0] = cq[j][1] = 0.f; }
    }
#pragma unroll
    for (int mt = 0; mt < 2; mt++) {
        int row = warpm + mt * 16 + g8;
        float rs0 = rowscale ? rowscale[m0 + row] : 1.f;
        float rs1 = rowscale ? rowscale[m0 + row + 8] : 1.f;
#pragma unroll
        for (int nt = 0; nt < 8; nt++) {
            int col = warpn + nt * 8 + kc;
            float b0 = bias ? bias[col] : 0.f;
            float b1 = bias ? bias[col + 1] : 0.f;
            float v00 = (c[mt][nt][0] + b0) * rs0, v01 = (c[mt][nt][1] + b1) * rs0;
            float v10 = (c[mt][nt][2] + b0) * rs1, v11 = (c[mt][nt][3] + b1) * rs1;
            *reinterpret_cast<float2*>(Cb + (long long)row * 128 + col) = make_float2(v00, v01);
            *reinterpret_cast<float2*>(Cb + (long long)(row + 8) * 128 + col) = make_float2(v10, v11);
            if (STATS) {
                cs[nt][0] += v00 + v10; cq[nt][0] += v00 * v00 + v10 * v10;
                cs[nt][1] += v01 + v11; cq[nt][1] += v01 * v01 + v11 * v11;
            }
        }
    }
    if (STATS) {
        __syncthreads();
#pragma unroll
        for (int nt = 0; nt < 8; nt++) {
            int col = warpn + nt * 8 + kc;
            atomicAdd(&sstat[col], cs[nt][0]);
            atomicAdd(&sstat[col + 1], cs[nt][1]);
            atomicAdd(&sstat[128 + col], cq[nt][0]);
            atomicAdd(&sstat[128 + col + 1], cq[nt][1]);
        }
        __syncthreads();
        if (t < 128) {
            atomicAdd(&g_sumA[t], sstat[t]);
            atomicAdd(&g_ssA[t], sstat[128 + t]);
        }
    }
}

// ================= warp-per-node aggregation (prescaled inputs, 8x unrolled) =================
// MODE 0: gcn+bias (+stats, fp32 out); 1: gcn+bias+softmax (fp32 + sT bf16); 2: plain sum (tT bf16)
template<int MODE>
__global__ __launch_bounds__(256) void k_aggw(
    const float* __restrict__ in, const float* __restrict__ bias, float* __restrict__ out,
    __nv_bfloat16* __restrict__ oTh, __nv_bfloat16* __restrict__ oTl)
{
    __shared__ float sred[8][128];
    __shared__ float st[8][132];
    int t = threadIdx.x, w = t >> 5, lane = t & 31;
    int i = blockIdx.x * 8 + w;
    int e0 = i * SLOTCAP;
    int n = g_deg[i];
    int npad = (n + 7) & ~7;
    if (npad > SLOTCAP) npad = SLOTCAP;
    float ax = 0.f, ay = 0.f, az = 0.f, aw = 0.f;
    for (int c0 = 0; c0 < npad; c0 += 32) {
        int m = npad - c0; if (m > 32) m = 32;
        int src = (lane < m) ? g_srcbuf[e0 + c0 + lane] : 0;
        for (int kk = 0; kk < m; kk += 8) {
#pragma unroll
            for (int u = 0; u < 8; u++) {
                int s = __shfl_sync(0xffffffffu, src, kk + u);
                float4 hv = *reinterpret_cast<const float4*>(in + (long long)s * 128 + lane * 4);
                ax += hv.x; ay += hv.y; az += hv.z; aw += hv.w;
            }
        }
    }
    float di = g_dinv[i];
    float vx, vy, vz, vw;
    if (MODE != 2) {
        // in rows are dinv-prescaled: out_i = di*(sum_j hs_j + hs_i) + bias
        float4 hv = *reinterpret_cast<const float4*>(in + (long long)i * 128 + lane * 4);
        vx = di * (ax + hv.x) + bias[lane * 4 + 0];
        vy = di * (ay + hv.y) + bias[lane * 4 + 1];
        vz = di * (az + hv.z) + bias[lane * 4 + 2];
        vw = di * (aw + hv.w) + bias[lane * 4 + 3];
    } else {
        vx = ax; vy = ay; vz = az; vw = aw;
    }
    if (MODE == 1) {
        float mx = fmaxf(fmaxf(vx, vy), fmaxf(vz, vw));
#pragma unroll
        for (int o = 16; o; o >>= 1) mx = fmaxf(mx, __shfl_xor_sync(0xffffffffu, mx, o));
        vx = __expf(vx - mx); vy = __expf(vy - mx); vz = __expf(vz - mx); vw = __expf(vw - mx);
        float sm = vx + vy + vz + vw;
#pragma unroll
        for (int o = 16; o; o >>= 1) sm += __shfl_xor_sync(0xffffffffu, sm, o);
        float inv = 1.f / sm;
        vx *= inv; vy *= inv; vz *= inv; vw *= inv;
    }
    if (MODE != 2) {
        float4 o4 = { vx, vy, vz, vw };
        *reinterpret_cast<float4*>(out + (long long)i * 128 + lane * 4) = o4;
    }
    if (MODE == 0) {
        sred[w][lane * 4 + 0] = vx; sred[w][lane * 4 + 1] = vy;
        sred[w][lane * 4 + 2] = vz; sred[w][lane * 4 + 3] = vw;
        __syncthreads();
        if (t < 128) {
            float s = 0.f, q = 0.f;
#pragma unroll
            for (int ww = 0; ww < 8; ww++) { float v = sred[ww][t]; s += v; q += v * v; }
            atomicAdd(&g_sumB[t], s);
            atomicAdd(&g_ssB[t], q);
        }
    } else {
        st[w][lane * 4 + 0] = vx; st[w][lane * 4 + 1] = vy;
        st[w][lane * 4 + 2] = vz; st[w][lane * 4 + 3] = vw;
        __syncthreads();
        if (t < 128) {
            int c = t;
            float v0 = st[0][c], v1 = st[1][c], v2 = st[2][c], v3 = st[3][c];
            float v4 = st[4][c], v5 = st[5][c], v6 = st[6][c], v7 = st[7][c];
            long long o = (long long)c * NNODES + blockIdx.x * 8;
            uint4 hv, lv;
            hv.x = pack_hi(v0, v1); hv.y = pack_hi(v2, v3);
            hv.z = pack_hi(v4, v5); hv.w = pack_hi(v6, v7);
            lv.x = pack_lo(v0, v1); lv.y = pack_lo(v2, v3);
            lv.z = pack_lo(v4, v5); lv.w = pack_lo(v6, v7);
            *reinterpret_cast<uint4*>(oTh + o) = hv;
            *reinterpret_cast<uint4*>(oTl + o) = lv;
        }
    }
}

// agg of prescaled x (64 ch) -> row-major bf16 hi/lo
__global__ __launch_bounds__(256) void k_aggx() {
    int t = threadIdx.x, w = t >> 5, lane = t & 31;
    int i = blockIdx.x * 8 + w;
    int e0 = i * SLOTCAP;
    int n = g_deg[i];
    int npad = (n + 7) & ~7;
    if (npad > SLOTCAP) npad = SLOTCAP;
    float ax = 0.f, ay = 0.f;
    for (int c0 = 0; c0 < npad; c0 += 32) {
        int m = npad - c0; if (m > 32) m = 32;
        int src = (lane < m) ? g_srcbuf[e0 + c0 + lane] : 0;
        for (int kk = 0; kk < m; kk += 8) {
#pragma unroll
            for (int u = 0; u < 8; u++) {
                int s = __shfl_sync(0xffffffffu, src, kk + u);
                float2 hv = *reinterpret_cast<const float2*>(g_xs + (long long)s * 64 + lane * 2);
                ax += hv.x; ay += hv.y;
            }
        }
    }
    float di = g_dinv[i];
    float2 hv = *reinterpret_cast<const float2*>(g_xs + (long long)i * 64 + lane * 2);
    ax = di * (ax + hv.x);
    ay = di * (ay + hv.y);
    long long o = (long long)i * 64 + lane * 2;
    *reinterpret_cast<uint32_t*>(g_axh + o) = pack_hi(ax, ay);
    *reinterpret_cast<uint32_t*>(g_axl + o) = pack_lo(ax, ay);
}

// ================= BN+SiLU(+res); fp32 h (opt), row bf16, trans bf16 (opt) =================
template<bool RES, bool WH, bool WT>
__global__ __launch_bounds__(256) void k_bn(
    const float* __restrict__ y, const float* __restrict__ res, float* __restrict__ h,
    __nv_bfloat16* __restrict__ rh, __nv_bfloat16* __restrict__ rl,
    __nv_bfloat16* __restrict__ th, __nv_bfloat16* __restrict__ tl,
    const float* __restrict__ gw, const float* __restrict__ be,
    const float* __restrict__ sumArr, const float* __restrict__ ssArr)
{
    __shared__ float tile[32][33];
    __shared__ float sc[32], sh[32];
    int t = threadIdx.x;
    int n0 = blockIdx.x * 32, c0 = blockIdx.y * 32;
    if (t < 32) {
        int c = c0 + t;
        float m = sumArr[c] * (1.f / NNODES);
        float var = ssArr[c] * (1.f / NNODES) - m * m;
        float s = gw[c] * rsqrtf(var + 1e-5f);
        sc[t] = s;
        sh[t] = be[c] - s * m;
    }
    __syncthreads();
    int nl = t >> 3, cg = t & 7;
    long long idx = (long long)(n0 + nl) * 128 + c0 + cg * 4;
    float4 v = *reinterpret_cast<const float4*>(y + idx);
    float o0, o1, o2, o3;
    {
        float a;
        a = sc[cg * 4 + 0] * v.x + sh[cg * 4 + 0]; o0 = a / (1.f + __expf(-a));
        a = sc[cg * 4 + 1] * v.y + sh[cg * 4 + 1]; o1 = a / (1.f + __expf(-a));
        a = sc[cg * 4 + 2] * v.z + sh[cg * 4 + 2]; o2 = a / (1.f + __expf(-a));
        a = sc[cg * 4 + 3] * v.w + sh[cg * 4 + 3]; o3 = a / (1.f + __expf(-a));
    }
    if (RES) {
        float4 r = *reinterpret_cast<const float4*>(res + idx);
        o0 += r.x; o1 += r.y; o2 += r.z; o3 += r.w;
    }
    if (WH) {
        float4 ov = { o0, o1, o2, o3 };
        *reinterpret_cast<float4*>(h + idx) = ov;
    }
    {
        uint2 hv, lv;
        hv.x = pack_hi(o0, o1); hv.y = pack_hi(o2, o3);
        lv.x = pack_lo(o0, o1); lv.y = pack_lo(o2, o3);
        *reinterpret_cast<uint2*>(rh + idx) = hv;
        *reinterpret_cast<uint2*>(rl + idx) = lv;
    }
    if (WT) {
        tile[nl][cg * 4 + 0] = o0; tile[nl][cg * 4 + 1] = o1;
        tile[nl][cg * 4 + 2] = o2; tile[nl][cg * 4 + 3] = o3;
        __syncthreads();
        int cc = t >> 3, g = t & 7;
        float w0 = tile[g * 4 + 0][cc], w1 = tile[g * 4 + 1][cc];
        float w2 = tile[g * 4 + 2][cc], w3 = tile[g * 4 + 3][cc];
        long long o = (long long)(c0 + cc) * NNODES + n0 + g * 4;
        uint2 hv, lv;
        hv.x = pack_hi(w0, w1); hv.y = pack_hi(w2, w3);
        lv.x = pack_lo(w0, w1); lv.y = pack_lo(w2, w3);
        *reinterpret_cast<uint2*>(th + o) = hv;
        *reinterpret_cast<uint2*>(tl + o) = lv;
    }
}

// ================= reduce partials + dinv2 + An; reset stack-2 state =================
__global__ __launch_bounds__(256) void k_reduce_an() {
    int b = blockIdx.x, t = threadIdx.x;
    if (b == 0 && t < 128) {
        g_s2a[t] = 0.f; g_q2a[t] = 0.f; g_s2b[t] = 0.f; g_q2b[t] = 0.f;
        if (t == 0) g_bar = 0;
    }
    const long long PS = (long long)NB * CH * CH;
    const long long BO = (long long)b * CH * CH;
    __shared__ float sd[128];
    for (int idx = t; idx < CH * CH; idx += 256) {
        float s = 0.f;
#pragma unroll
        for (int p = 0; p < 8; p++) s += g_xpart[p * PS + BO + idx];
        g_x2[BO + idx] = s;
    }
    int w = t >> 5, lane = t & 31;
    for (int r = w; r < 128; r += 8) {
        float rsum = 0.f;
#pragma unroll
        for (int q = 0; q < 4; q++) {
            int idx = r * 128 + lane + q * 32;
            float s = 0.f;
#pragma unroll
            for (int p = 0; p < 8; p++) s += g_apart[p * PS + BO + idx];
            g_A2[BO + idx] = s;
            rsum += s;
        }
#pragma unroll
        for (int o = 16; o; o >>= 1) rsum += __shfl_down_sync(0xffffffffu, rsum, o);
        if (lane == 0) sd[r] = rsqrtf(rsum + 1.0f);
    }
    __syncthreads();
    for (int idx = t; idx < CH * CH; idx += 256) {
        int i = idx >> 7, j = idx & 127;
        float v = g_A2[BO + idx] + (i == j ? 1.f : 0.f);
        g_An[BO + idx] = sd[i] * v * sd[j];
    }
}

// ================= fused stack-2 (FFMA2, 32 blocks, grid barrier) =================
__device__ __forceinline__ void gridbar(int target) {
    __syncthreads();
    __threadfence();
    if (threadIdx.x == 0) {
        atomicAdd(&g_bar, 1);
        while (*(volatile int*)&g_bar < target) __nanosleep(64);
    }
    __syncthreads();
    __threadfence();
}

__device__ __forceinline__ void gemm_sm128(const float* __restrict__ P, const float* __restrict__ Q,
                                           unsigned long long acc2[8][4], int tx, int ty)
{
#pragma unroll
    for (int i = 0; i < 8; i++)
#pragma unroll
        for (int j = 0; j < 4; j++) acc2[i][j] = 0ull;
#pragma unroll 2
    for (int k = 0; k < 128; k++) {
        float a[8];
#pragma unroll
        for (int i = 0; i < 8; i++) a[i] = P[(ty * 8 + i) * 128 + k];
        const unsigned long long* Qp =
            reinterpret_cast<const unsigned long long*>(&Q[k * 128 + tx * 8]);
        unsigned long long b0 = Qp[0], b1 = Qp[1], b2 = Qp[2], b3 = Qp[3];
#pragma unroll
        for (int i = 0; i < 8; i++) {
            unsigned long long ad = dup_f32(a[i]);
            ffma2(acc2[i][0], ad, b0);
            ffma2(acc2[i][1], ad, b1);
            ffma2(acc2[i][2], ad, b2);
            ffma2(acc2[i][3], ad, b3);
        }
    }
}

__global__ __launch_bounds__(256) void k_stack2(
    const float* __restrict__ w2a, const float* __restrict__ b2a,
    const float* __restrict__ g2a, const float* __restrict__ be2a,
    const float* __restrict__ w2b, const float* __restrict__ b2b,
    const float* __restrict__ g2b, const float* __restrict__ be2b,
    const float* __restrict__ wl, const float* __restrict__ bl,
    float* __restrict__ out, int out_size)
{
    extern __shared__ __align__(16) float sm2[];
    float* AN = sm2;
    float* XB = sm2 + 16384;
    float* WB = sm2 + 32768;
    __shared__ float red[2048];
    __shared__ float gv[128];
    __shared__ float lg[10];
    __shared__ float lse;
    int b = blockIdx.x, t = threadIdx.x, tx = t & 15, ty = t >> 4;
    const float INVN = 1.f / (NB * CH);

    {
        const float4* pAn = (const float4*)(g_An + (long long)b * 16384);
        const float4* pX2 = (const float4*)(g_x2 + (long long)b * 16384);
        const float4* pWa = (const float4*)w2a;
        float4* An4 = (float4*)AN; float4* X4 = (float4*)XB; float4* W4 = (float4*)WB;
        for (int i = t; i < 4096; i += 256) { An4[i] = pAn[i]; X4[i] = pX2[i]; W4[i] = pWa[i]; }
    }
    __syncthreads();

    unsigned long long acc2[8][4];
    float cs[8], cq[8];

    gemm_sm128(XB, WB, acc2, tx, ty);
    __syncthreads();
#pragma unroll
    for (int i = 0; i < 8; i++)
#pragma unroll
        for (int j = 0; j < 4; j++) {
            float2 p = u2f(acc2[i][j]);
            XB[(ty * 8 + i) * 128 + tx * 8 + 2 * j] = p.x;
            XB[(ty * 8 + i) * 128 + tx * 8 + 2 * j + 1] = p.y;
        }
    __syncthreads();

    gemm_sm128(AN, XB, acc2, tx, ty);
    __syncthreads();
#pragma unroll
    for (int j = 0; j < 8; j++) { cs[j] = 0.f; cq[j] = 0.f; }
#pragma unroll
    for (int i = 0; i < 8; i++)
#pragma unroll
        for (int j = 0; j < 4; j++) {
            float2 p = u2f(acc2[i][j]);
            float v0 = p.x + b2a[tx * 8 + 2 * j];
            float v1 = p.y + b2a[tx * 8 + 2 * j + 1];
            WB[(ty * 8 + i) * 128 + tx * 8 + 2 * j] = v0;
            WB[(ty * 8 + i) * 128 + tx * 8 + 2 * j + 1] = v1;
            cs[2 * j] += v0; cq[2 * j] += v0 * v0;
            cs[2 * j + 1] += v1; cq[2 * j + 1] += v1 * v1;
        }
#pragma unroll
    for (int j = 0; j < 8; j++) red[ty * 128 + tx * 8 + j] = cs[j];
    __syncthreads();
    if (t < 128) { float s = 0.f; for (int g = 0; g < 16; g++) s += red[g * 128 + t]; atomicAdd(&g_s2a[t], s); }
    __syncthreads();
#pragma unroll
    for (int j = 0; j < 8; j++) red[ty * 128 + tx * 8 + j] = cq[j];
    __syncthreads();
    if (t < 128) { float s = 0.f; for (int g = 0; g < 16; g++) s += red[g * 128 + t]; atomicAdd(&g_q2a[t], s); }

    gridbar(NB);

    float scv[8], shv[8];
#pragma unroll
    for (int j = 0; j < 8; j++) {
        int c = tx * 8 + j;
        float m = g_s2a[c] * INVN;
        float var = g_q2a[c] * INVN - m * m;
        float s = g2a[c] * rsqrtf(var + 1e-5f);
        scv[j] = s; shv[j] = be2a[c] - s * m;
    }
#pragma unroll
    for (int i = 0; i < 8; i++)
#pragma unroll
        for (int j = 0; j < 8; j++) {
            float v = WB[(ty * 8 + i) * 128 + tx * 8 + j];
            v = scv[j] * v + shv[j];
            v = v / (1.f + __expf(-v));
            XB[(ty * 8 + i) * 128 + tx * 8 + j] = v;
        }
    __syncthreads();

    {
        const float4* pWb = (const float4*)w2b;
        float4* W4 = (float4*)WB;
        for (int i = t; i < 4096; i += 256) W4[i] = pWb[i];
    }
    __syncthreads();

    gemm_sm128(XB, WB, acc2, tx, ty);
    __syncthreads();
#pragma unroll
    for (int i = 0; i < 8; i++)
#pragma unroll
        for (int j = 0; j < 4; j++) {
            float2 p = u2f(acc2[i][j]);
            WB[(ty * 8 + i) * 128 + tx * 8 + 2 * j] = p.x;
            WB[(ty * 8 + i) * 128 + tx * 8 + 2 * j + 1] = p.y;
        }
    __syncthreads();

    gemm_sm128(AN, WB, acc2, tx, ty);
#pragma unroll
    for (int j = 0; j < 8; j++) { cs[j] = 0.f; cq[j] = 0.f; }
#pragma unroll
    for (int i = 0; i < 8; i++)
#pragma unroll
        for (int j = 0; j < 4; j++) {
            float2 p = u2f(acc2[i][j]);
            float v0 = p.x + b2b[tx * 8 + 2 * j];
            float v1 = p.y + b2b[tx * 8 + 2 * j + 1];
            cs[2 * j] += v0; cq[2 * j] += v0 * v0;
            cs[2 * j + 1] += v1; cq[2 * j + 1] += v1 * v1;
        }
    __syncthreads();
#pragma unroll
    for (int j = 0; j < 8; j++) red[ty * 128 + tx * 8 + j] = cs[j];
    __syncthreads();
    if (t < 128) { float s = 0.f; for (int g = 0; g < 16; g++) s += red[g * 128 + t]; atomicAdd(&g_s2b[t], s); }
    __syncthreads();
#pragma unroll
    for (int j = 0; j < 8; j++) red[ty * 128 + tx * 8 + j] = cq[j];
    __syncthreads();
    if (t < 128) { float s = 0.f; for (int g = 0; g < 16; g++) s += red[g * 128 + t]; atomicAdd(&g_q2b[t], s); }

    gridbar(2 * NB);

#pragma unroll
    for (int j = 0; j < 8; j++) {
        int c = tx * 8 + j;
        float m = g_s2b[c] * INVN;
        float var = g_q2b[c] * INVN - m * m;
        float s = g2b[c] * rsqrtf(var + 1e-5f);
        scv[j] = s; shv[j] = be2b[c] - s * m;
    }
    float colsum[8];
#pragma unroll
    for (int j = 0; j < 8; j++) colsum[j] = 0.f;
#pragma unroll
    for (int i = 0; i < 8; i++)
#pragma unroll
        for (int j = 0; j < 4; j++) {
            float2 p = u2f(acc2[i][j]);
            float v0 = scv[2 * j] * (p.x + b2b[tx * 8 + 2 * j]) + shv[2 * j];
            float v1 = scv[2 * j + 1] * (p.y + b2b[tx * 8 + 2 * j + 1]) + shv[2 * j + 1];
            v0 = v0 / (1.f + __expf(-v0));
            v1 = v1 / (1.f + __expf(-v1));
            v0 += XB[(ty * 8 + i) * 128 + tx * 8 + 2 * j];
            v1 += XB[(ty * 8 + i) * 128 + tx * 8 + 2 * j + 1];
            colsum[2 * j] += v0;
            colsum[2 * j + 1] += v1;
        }
    __syncthreads();
#pragma unroll
    for (int j = 0; j < 8; j++) red[ty * 128 + tx * 8 + j] = colsum[j];
    __syncthreads();
    if (t < 128) {
        float s = 0.f;
        for (int g = 0; g < 16; g++) s += red[g * 128 + t];
        gv[t] = s * (1.f / 32.f);
    }
    __syncthreads();
    if (t < 10) {
        float a = bl[t];
        for (int k = 0; k < 128; k++) a += gv[k] * wl[k * 10 + t];
        lg[t] = a;
    }
    __syncthreads();
    if (t == 0) {
        float mx = -1e30f;
        for (int j = 0; j < 10; j++) mx = fmaxf(mx, lg[j]);
        float se = 0.f;
        for (int j = 0; j < 10; j++) se += expf(lg[j] - mx);
        lse = mx + logf(se);
    }
    __syncthreads();
    if (t < 10) {
        int o = b * 10 + t;
        if (o < out_size) out[o] = lg[t] - lse;
    }
    if (b == 0) {
        for (int idx = NB * 10 + t; idx < out_size; idx += 256) out[idx] = 0.f;
    }
}

// ================= host orchestration =================
extern "C" void kernel_launch(void* const* d_in, const int* in_sizes, int n_in,
                              void* d_out, int out_size) {
    const float* x    = (const float*)d_in[0];
    const int*   ei   = (const int*)  d_in[1];
    const float* w1a  = (const float*)d_in[4];
    const float* b1a  = (const float*)d_in[5];
    const float* g1a  = (const float*)d_in[6];
    const float* be1a = (const float*)d_in[7];
    const float* w1b  = (const float*)d_in[8];
    const float* b1b  = (const float*)d_in[9];
    const float* g1b  = (const float*)d_in[10];
    const float* be1b = (const float*)d_in[11];
    const float* wp1  = (const float*)d_in[12];
    const float* bp1  = (const float*)d_in[13];
    const float* w2a  = (const float*)d_in[14];
    const float* b2a  = (const float*)d_in[15];
    const float* g2a  = (const float*)d_in[16];
    const float* be2a = (const float*)d_in[17];
    const float* w2b  = (const float*)d_in[18];
    const float* b2b  = (const float*)d_in[19];
    const float* g2b  = (const float*)d_in[20];
    const float* be2b = (const float*)d_in[21];
    const float* wl   = (const float*)d_in[24];
    const float* bl   = (const float*)d_in[25];
    float* outp = (float*)d_out;
    (void)n_in; (void)in_sizes;

    float *p_lin, *p_y, *p_h, *p_s, *p_xpart, *p_apart;
    float *p_sumA, *p_ssA, *p_sumB, *p_ssB, *p_dinv;
    __nv_bfloat16 *p_axh, *p_axl, *p_hah, *p_hal, *p_hbh, *p_hbl;
    __nv_bfloat16 *p_hTh, *p_hTl, *p_sTh, *p_sTl, *p_tTh, *p_tTl;
    __nv_bfloat16 *p_w1ah, *p_w1al, *p_w1bh, *p_w1bl, *p_wp1h, *p_wp1l;
    cudaGetSymbolAddress((void**)&p_lin,   g_lin);
    cudaGetSymbolAddress((void**)&p_y,     g_y);
    cudaGetSymbolAddress((void**)&p_h,     g_h);
    cudaGetSymbolAddress((void**)&p_s,     g_s);
    cudaGetSymbolAddress((void**)&p_xpart, g_xpart);
    cudaGetSymbolAddress((void**)&p_apart, g_apart);
    cudaGetSymbolAddress((void**)&p_sumA,  g_sumA);
    cudaGetSymbolAddress((void**)&p_ssA,   g_ssA);
    cudaGetSymbolAddress((void**)&p_sumB,  g_sumB);
    cudaGetSymbolAddress((void**)&p_ssB,   g_ssB);
    cudaGetSymbolAddress((void**)&p_dinv,  g_dinv);
    cudaGetSymbolAddress((void**)&p_axh,   g_axh);
    cudaGetSymbolAddress((void**)&p_axl,   g_axl);
    cudaGetSymbolAddress((void**)&p_hah,   g_hah);
    cudaGetSymbolAddress((void**)&p_hal,   g_hal);
    cudaGetSymbolAddress((void**)&p_hbh,   g_hbh);
    cudaGetSymbolAddress((void**)&p_hbl,   g_hbl);
    cudaGetSymbolAddress((void**)&p_hTh,   g_hTh);
    cudaGetSymbolAddress((void**)&p_hTl,   g_hTl);
    cudaGetSymbolAddress((void**)&p_sTh,   g_sTh);
    cudaGetSymbolAddress((void**)&p_sTl,   g_sTl);
    cudaGetSymbolAddress((void**)&p_tTh,   g_tTh);
    cudaGetSymbolAddress((void**)&p_tTl,   g_tTl);
    cudaGetSymbolAddress((void**)&p_w1ah,  g_w1ah);
    cudaGetSymbolAddress((void**)&p_w1al,  g_w1al);
    cudaGetSymbolAddress((void**)&p_w1bh,  g_w1bh);
    cudaGetSymbolAddress((void**)&p_w1bl,  g_w1bl);
    cudaGetSymbolAddress((void**)&p_wp1h,  g_wp1h);
    cudaGetSymbolAddress((void**)&p_wp1l,  g_wp1l);

    static bool attrDone = false;
    if (!attrDone) {
        cudaFuncSetAttribute(k_stack2, cudaFuncAttributeMaxDynamicSharedMemorySize, 196608);
        cudaFuncSetAttribute(k_mma<false, true>,  cudaFuncAttributeMaxDynamicSharedMemorySize, 50176);
        cudaFuncSetAttribute(k_mma<false, false>, cudaFuncAttributeMaxDynamicSharedMemorySize, 50176);
        cudaFuncSetAttribute(k_mma<true, false>,  cudaFuncAttributeMaxDynamicSharedMemorySize, 50176);
        attrDone = true;
    }

    // graph structure (one-pass CSR) + pad + weight split + dinv + x prescale
    k_zero_deg<<<NNODES / 256, 256>>>();
    k_build<<<NEDGES / 256, 256>>>(ei);
    k_wsplit<<<160, 256>>>(w1a, w1b, wp1);
    k_xscale<<<NNODES / 8, 256>>>(x);

    // stack 1, layer a
    k_aggx<<<NNODES / 8, 256>>>();
    k_mma<false, true><<<256, 256, 50176>>>(p_axh, p_axl, 64,
                                            p_w1ah, p_w1al, nullptr, nullptr, 64,
                                            b1a, nullptr, p_y, nullptr, 64);
    k_bn<false, true, false><<<dim3(NNODES / 32, 4), 256>>>(
        p_y, nullptr, p_h, p_hah, p_hal, nullptr, nullptr, g1a, be1a, p_sumA, p_ssA);

    // stack 1, layer b (residual); GEMM output prescaled by dinv
    k_mma<false, false><<<256, 256, 50176>>>(p_hah, p_hal, 128,
                                             p_w1bh, p_w1bl, nullptr, nullptr, 128,
                                             nullptr, p_dinv, p_lin, nullptr, 128);
    k_aggw<0><<<NNODES / 8, 256>>>(p_lin, b1b, p_y, nullptr, nullptr);
    k_bn<true, false, true><<<dim3(NNODES / 32, 4), 256>>>(
        p_y, p_h, nullptr, p_hbh, p_hbl, p_hTh, p_hTl, g1b, be1b, p_sumB, p_ssB);

    // pooling 1; GEMM output prescaled by dinv
    k_mma<false, false><<<256, 256, 50176>>>(p_hbh, p_hbl, 128,
                                             p_wp1h, p_wp1l, nullptr, nullptr, 128,
                                             nullptr, p_dinv, p_lin, nullptr, 128);
    k_aggw<1><<<NNODES / 8, 256>>>(p_lin, bp1, p_s, p_sTh, p_sTl);
    k_aggw<2><<<NNODES / 8, 256>>>(p_s, nullptr, nullptr, p_tTh, p_tTl);

    // pooled einsums + reduce/An
    k_mma<true, false><<<dim3(1, 16, NB), 256, 50176>>>(p_sTh, p_sTl, NNODES,
                                                        p_hTh, p_hTl, p_tTh, p_tTl, NNODES,
                                                        nullptr, nullptr, p_xpart, p_apart, 128);
    k_reduce_an<<<NB, 256>>>();

    // fused stack 2 (FFMA2) + head
    k_stack2<<<NB, 256, 196608>>>(w2a, b2a, g2a, be2a, w2b, b2b, g2b, be2b, wl, bl, outp, out_size);
}